// round 7
// baseline (speedup 1.0000x reference)
#include <cuda_runtime.h>
#include <cuda_fp16.h>
#include <math.h>

#define N_NODES 20000
#define N_EDGES 320000
#define NPB 8
#define NPN 4     // nodes per prop block (2 warps each)

// ---------------- device scratch ----------------
__device__ float  g_xA[N_NODES*13*32];
__device__ float  g_xB[N_NODES*13*32];
__device__ __half g_h [N_NODES*12*32];
__device__ float  g_acc[N_NODES*12*32];
__device__ __half g_pA[N_NODES*12*32];
__device__ __half g_pB[N_NODES*12*32];
__device__ float  g_hl[8*N_NODES*32];
__device__ int    g_rowptr[N_NODES+1];
__device__ int    g_curs[N_NODES];
__device__ int    g_cnt[N_NODES];
__device__ float  g_invdeg[N_NODES];
__device__ int    g_col[N_EDGES];
__device__ double g_statsS[32*64];
__device__ float  g_affine[64];
__device__ int    g_done;

__device__ __forceinline__ __half2 H2(unsigned int u){ return *reinterpret_cast<__half2*>(&u); }
__device__ __forceinline__ unsigned int U2(__half2 h){ return *reinterpret_cast<unsigned int*>(&h); }

// ---------------- setup ----------------
__global__ void k_hist(const int* __restrict__ dst){
    int i = blockIdx.x*256 + threadIdx.x;
    if(i < 64) g_affine[i] = (i < 32) ? 1.f : 0.f;
    if(i < N_EDGES) atomicAdd(&g_cnt[dst[i]], 1);
}

__global__ void k_scan(){
    const int CH = 20;
    int tid = threadIdx.x;
    int b0 = tid*CH; if(b0 > N_NODES) b0 = N_NODES;
    int b1 = b0 + CH; if(b1 > N_NODES) b1 = N_NODES;
    int sum = 0;
    for(int i = b0; i < b1; i++) sum += g_cnt[i];
    int lane = tid & 31, w = tid >> 5;
    int v = sum;
#pragma unroll
    for(int o = 1; o < 32; o <<= 1){
        int t = __shfl_up_sync(0xffffffffu, v, o);
        if(lane >= o) v += t;
    }
    __shared__ int wsum[32];
    if(lane == 31) wsum[w] = v;
    __syncthreads();
    if(w == 0){
        int x = wsum[lane];
#pragma unroll
        for(int o = 1; o < 32; o <<= 1){
            int t = __shfl_up_sync(0xffffffffu, x, o);
            if(lane >= o) x += t;
        }
        wsum[lane] = x;
    }
    __syncthreads();
    int pre = v - sum + ((w > 0) ? wsum[w-1] : 0);
    int run = pre;
    for(int i = b0; i < b1; i++){
        int c = g_cnt[i];
        g_curs[i] = run;
        run += c;
        g_rowptr[i+1] = run;
        g_invdeg[i] = 1.f/(float)(c > 0 ? c : 1);
        g_cnt[i] = 0;
    }
    if(tid == 0) g_rowptr[0] = 0;
}

__global__ void k_fill(const int* __restrict__ src, const int* __restrict__ dst){
    int e = blockIdx.x*256 + threadIdx.x;
    if(e < N_EDGES){
        int pos = atomicAdd(&g_curs[dst[e]], 1);
        g_col[pos] = src[e];
    }
}

// ---------------- gated dilated conv (+enter fusion) + h@W0 + hl ----------------
template<int TIN, int D, bool ENTER, bool LAST>
__global__ void __launch_bounds__(32*NPB) k_conv(
    const float* __restrict__ xin,
    const float* __restrict__ ew, const float* __restrict__ eb,
    const float* __restrict__ fw_g, const float* __restrict__ fb_g,
    const float* __restrict__ gw_g, const float* __restrict__ gb_g,
    const float* __restrict__ w0_g,
    float* __restrict__ hl_out, float* __restrict__ xsave)
{
    constexpr int TOUT = TIN - D;
    constexpr int NQ   = (TIN + 3)/4;
    constexpr int TP   = 20;
    extern __shared__ float sm[];
    float* wq  = sm;
    float* w0  = sm + 4096;
    float* ews = sm + 4096 + (LAST ? 0 : 1024);
    float* xs  = ews + (ENTER ? 128 : 0);

    int tx = threadIdx.x, ty = threadIdx.y;
    int tid = ty*32 + tx;
    for(int j = tid; j < 1024; j += 32*NPB){
        int o = j & 31, i = j >> 5;
        float4 v;
        v.x = fw_g[(o*32+i)*2+0];
        v.y = fw_g[(o*32+i)*2+1];
        v.z = gw_g[(o*32+i)*2+0];
        v.w = gw_g[(o*32+i)*2+1];
        ((float4*)wq)[j] = v;
    }
    if(!LAST) for(int j = tid; j < 1024; j += 32*NPB) w0[j] = w0_g[j];
    if(ENTER){
        if(tid < 96) ews[tid] = ew[tid];
        if(tid < 32) ews[96+tid] = eb[tid];
    }
    __syncthreads();

    int n = blockIdx.x*NPB + ty;
    float* xrow = xs + ty*(32*TP);
    if(ENTER){
        const float* ip = xin + n*(TIN*3);
        float we0 = ews[tx*3+0], we1 = ews[tx*3+1], we2 = ews[tx*3+2], be = ews[96+tx];
#pragma unroll
        for(int tt = 0; tt < TIN; tt++){
            float v = be + we0*ip[tt*3+0] + we1*ip[tt*3+1] + we2*ip[tt*3+2];
            xrow[tx*TP+tt] = v;
            xsave[(n*TIN+tt)*32+tx] = v;
        }
    } else {
        float scl = g_affine[tx], bia = g_affine[32+tx];
        const float* xp = xin + n*(TIN*32);
#pragma unroll
        for(int tt = 0; tt < TIN; tt++)
            xrow[tx*TP+tt] = xp[tt*32+tx]*scl + bia;
    }
    __syncwarp();

    float f[TOUT], g[TOUT];
    float fb = fb_g[tx], gb = gb_g[tx];
#pragma unroll
    for(int t = 0; t < TOUT; t++){ f[t] = fb; g[t] = gb; }
#pragma unroll
    for(int i = 0; i < 32; i++){
        float4 w4 = ((const float4*)wq)[i*32+tx];
        const float4* xq = (const float4*)(xrow + i*TP);
        float xv[NQ*4];
#pragma unroll
        for(int q = 0; q < NQ; q++){
            float4 t4 = xq[q];
            xv[q*4+0] = t4.x; xv[q*4+1] = t4.y; xv[q*4+2] = t4.z; xv[q*4+3] = t4.w;
        }
#pragma unroll
        for(int tt = 0; tt < TIN; tt++){
            float x = xv[tt];
            if(tt < TOUT){ f[tt]   += w4.x*x; g[tt]   += w4.z*x; }
            if(tt >= D)  { f[tt-D] += w4.y*x; g[tt-D] += w4.w*x; }
        }
    }
    __syncwarp();

    if(!LAST){
        float hlast = 0.f;
#pragma unroll
        for(int t = 0; t < TOUT; t++){
            float h = tanhf(f[t]) * (1.f/(1.f + expf(-g[t])));
            xrow[tx*TP+t] = h;
            g_h[(n*TOUT+t)*32+tx] = __float2half_rn(h);
            if(t == TOUT-1) hlast = h;
        }
        hl_out[n*32+tx] = hlast;
        __syncwarp();

        float u[TOUT];
#pragma unroll
        for(int t = 0; t < TOUT; t++) u[t] = 0.f;
#pragma unroll
        for(int c = 0; c < 32; c++){
            float w = w0[c*32+tx];
            const float4* hq = (const float4*)(xrow + c*TP);
#pragma unroll
            for(int q = 0; q < NQ; q++){
                if(q*4 < TOUT){
                    float4 hv = hq[q];
                    u[q*4+0] += hv.x*w;
                    if(q*4+1 < TOUT) u[q*4+1] += hv.y*w;
                    if(q*4+2 < TOUT) u[q*4+2] += hv.z*w;
                    if(q*4+3 < TOUT) u[q*4+3] += hv.w*w;
                }
            }
        }
#pragma unroll
        for(int t = 0; t < TOUT; t++) g_acc[(n*TOUT+t)*32+tx] = u[t];
    } else {
        float h = tanhf(f[TOUT-1]) * (1.f/(1.f + expf(-g[TOUT-1])));
        hl_out[n*32+tx] = h;
    }
}

// ---------------- fp16 half-gather: warp takes edges (beg+half) step 2 ----------------
template<int T>
__device__ __forceinline__ void gather_half(const uint4* __restrict__ in,
                                            int beg, int end, int half,
                                            int lane, float* acc)
{
    constexpr int R  = T*4;
    constexpr int NV = (R + 31)/32;
#pragma unroll
    for(int k = 0; k < NV*8; k++) acc[k] = 0.f;
    int e = beg + half;
    for(; e + 6 < end; e += 8){
        int s0 = g_col[e], s1 = g_col[e+2], s2 = g_col[e+4], s3 = g_col[e+6];
        const uint4* r0 = in + s0*R;
        const uint4* r1 = in + s1*R;
        const uint4* r2 = in + s2*R;
        const uint4* r3 = in + s3*R;
        uint4 q0[NV], q1[NV], q2[NV], q3[NV];
#pragma unroll
        for(int v = 0; v < NV; v++){
            int idx = v*32 + lane;
            if(idx < R){
                q0[v] = r0[idx]; q1[v] = r1[idx]; q2[v] = r2[idx]; q3[v] = r3[idx];
            }
        }
#pragma unroll
        for(int v = 0; v < NV; v++){
            int idx = v*32 + lane;
            if(idx < R){
                __half2 px = __hadd2(__hadd2(H2(q0[v].x), H2(q1[v].x)), __hadd2(H2(q2[v].x), H2(q3[v].x)));
                __half2 py = __hadd2(__hadd2(H2(q0[v].y), H2(q1[v].y)), __hadd2(H2(q2[v].y), H2(q3[v].y)));
                __half2 pz = __hadd2(__hadd2(H2(q0[v].z), H2(q1[v].z)), __hadd2(H2(q2[v].z), H2(q3[v].z)));
                __half2 pw = __hadd2(__hadd2(H2(q0[v].w), H2(q1[v].w)), __hadd2(H2(q2[v].w), H2(q3[v].w)));
                float2 f;
                f = __half22float2(px); acc[v*8+0] += f.x; acc[v*8+1] += f.y;
                f = __half22float2(py); acc[v*8+2] += f.x; acc[v*8+3] += f.y;
                f = __half22float2(pz); acc[v*8+4] += f.x; acc[v*8+5] += f.y;
                f = __half22float2(pw); acc[v*8+6] += f.x; acc[v*8+7] += f.y;
            }
        }
    }
    for(; e < end; e += 2){
        int s0 = g_col[e];
        const uint4* r0 = in + s0*R;
#pragma unroll
        for(int v = 0; v < NV; v++){
            int idx = v*32 + lane;
            if(idx < R){
                uint4 q = r0[idx];
                float2 f;
                f = __half22float2(H2(q.x)); acc[v*8+0] += f.x; acc[v*8+1] += f.y;
                f = __half22float2(H2(q.y)); acc[v*8+2] += f.x; acc[v*8+3] += f.y;
                f = __half22float2(H2(q.z)); acc[v*8+4] += f.x; acc[v*8+5] += f.y;
                f = __half22float2(H2(q.w)); acc[v*8+6] += f.x; acc[v*8+7] += f.y;
            }
        }
    }
}

template<int T>
__device__ __forceinline__ void acc_to_tile(const float* acc, float* tile, int lane){
    constexpr int R  = T*4;
    constexpr int NV = (R + 31)/32;
#pragma unroll
    for(int v = 0; v < NV; v++){
        int idx = v*32 + lane;
        if(idx < R){
            int t = idx >> 2, c0 = (idx & 3) << 3;
            float4* tp = (float4*)(tile + t*32 + c0);
            tp[0] = make_float4(acc[v*8+0], acc[v*8+1], acc[v*8+2], acc[v*8+3]);
            tp[1] = make_float4(acc[v*8+4], acc[v*8+5], acc[v*8+6], acc[v*8+7]);
        }
    }
}

// epilogue chunk: a[t] for t in [TOFF, TOFF+TB), g_acc +=
template<int T, int TB, int TOFF>
__device__ __forceinline__ void epi_acc(const float* tile, const float* Wreg,
                                        float* ap)
{
    float a[TB];
#pragma unroll
    for(int t = 0; t < TB; t++) a[t] = 0.f;
    const float4* tp = (const float4*)tile;
#pragma unroll
    for(int c4 = 0; c4 < 8; c4++){
#pragma unroll
        for(int t = 0; t < TB; t++){
            float4 sv = tp[(TOFF+t)*8+c4];
            a[t] += sv.x*Wreg[c4*4+0] + sv.y*Wreg[c4*4+1] + sv.z*Wreg[c4*4+2] + sv.w*Wreg[c4*4+3];
        }
    }
#pragma unroll
    for(int t = 0; t < TB; t++) ap[(TOFF+t)*32] += a[t];
}

// ---------------- diffusion hop (pair-split): cur = A*in ; g_acc += cur @ Wk ----------------
template<int T>
__global__ void __launch_bounds__(64*NPN) k_prop(
    const __half* __restrict__ in, __half* __restrict__ curout,
    const float* __restrict__ Wk)
{
    constexpr int R = T*4;
    __shared__ float Ws[1024];
    __shared__ __align__(16) float smP[2*NPN*12*32];
    int tid = threadIdx.x, lane = tid & 31, wid = tid >> 5;
    int p = wid >> 1, half = wid & 1;
    for(int j = tid; j < 1024; j += 64*NPN) Ws[j] = Wk[j];
    __syncthreads();

    int n = blockIdx.x*NPN + p;
    int beg = g_rowptr[n], end = g_rowptr[n+1];
    constexpr int NV = (R + 31)/32;
    float acc[NV*8];
    gather_half<T>((const uint4*)in, beg, end, half, lane, acc);
    acc_to_tile<T>(acc, smP + wid*(T*32), lane);
    __syncthreads();

    // combine pair partials into tile A; store curout (fp16)
    float* A = smP + (p*2)*(T*32);
    float* B = smP + (p*2+1)*(T*32);
    float4* A4 = (float4*)A;
    const float4* B4 = (const float4*)B;
    uint2* cp = (uint2*)(curout + n*(T*32));
    float iv = g_invdeg[n];
    constexpr int HF4 = T*4;      // float4s per warp (total T*8)
    for(int k = lane; k < HF4; k += 32){
        int j = half*HF4 + k;
        float4 a4 = A4[j], b4 = B4[j];
        a4.x = (a4.x + b4.x)*iv;
        a4.y = (a4.y + b4.y)*iv;
        a4.z = (a4.z + b4.z)*iv;
        a4.w = (a4.w + b4.w)*iv;
        A4[j] = a4;
        uint2 q;
        q.x = U2(__floats2half2_rn(a4.x, a4.y));
        q.y = U2(__floats2half2_rn(a4.z, a4.w));
        cp[j] = q;
    }
    __syncthreads();

    float Wreg[32];
#pragma unroll
    for(int c = 0; c < 32; c++) Wreg[c] = Ws[c*32+lane];
    float* ap = g_acc + n*(T*32) + lane;
    constexpr int TH = (T+1)/2;
    if(half == 0) epi_acc<T, TH, 0>(A, Wreg, ap);
    else          epi_acc<T, T-TH, TH>(A, Wreg, ap);
}

// finalize chunk: xnew for t-range; returns partial BN sums
template<int T, int TIN, int TB, int TOFF>
__device__ __forceinline__ void epi_fin(const float* tile, const float* Wreg,
    const float* ao, const float* xo, float* xn,
    float scl, float bia, float gb, float& sum, float& sq)
{
    float a[TB];
#pragma unroll
    for(int t = 0; t < TB; t++) a[t] = 0.f;
    const float4* tp = (const float4*)tile;
#pragma unroll
    for(int c4 = 0; c4 < 8; c4++){
#pragma unroll
        for(int t = 0; t < TB; t++){
            float4 sv = tp[(TOFF+t)*8+c4];
            a[t] += sv.x*Wreg[c4*4+0] + sv.y*Wreg[c4*4+1] + sv.z*Wreg[c4*4+2] + sv.w*Wreg[c4*4+3];
        }
    }
#pragma unroll
    for(int t = 0; t < TB; t++){
        float v = a[t] + ao[(TOFF+t)*32] + gb + xo[(TOFF+t)*32]*scl + bia;
        xn[(TOFF+t)*32] = v;
        sum += v; sq += v*v;
    }
}

// ---------------- hop 3 fused with finalize (pair-split) ----------------
template<int T, int TIN>
__global__ void __launch_bounds__(64*NPN) k_propfin(
    const __half* __restrict__ in, const float* __restrict__ Wk,
    const float* __restrict__ xold, float* __restrict__ xnew,
    const float* __restrict__ gcb,
    const float* __restrict__ bng, const float* __restrict__ bnb, float invCnt)
{
    constexpr int R = T*4;
    __shared__ float Ws[1024];
    __shared__ __align__(16) float smP[2*NPN*12*32];
    __shared__ float rs[64*NPN], rq[64*NPN];
    __shared__ int isLast;
    int tid = threadIdx.x, lane = tid & 31, wid = tid >> 5;
    int p = wid >> 1, half = wid & 1;
    for(int j = tid; j < 1024; j += 64*NPN) Ws[j] = Wk[j];
    __syncthreads();

    int n = blockIdx.x*NPN + p;
    int beg = g_rowptr[n], end = g_rowptr[n+1];
    constexpr int NV = (R + 31)/32;
    float acc[NV*8];
    gather_half<T>((const uint4*)in, beg, end, half, lane, acc);
    acc_to_tile<T>(acc, smP + wid*(T*32), lane);
    __syncthreads();

    float* A = smP + (p*2)*(T*32);
    float* B = smP + (p*2+1)*(T*32);
    float4* A4 = (float4*)A;
    const float4* B4 = (const float4*)B;
    float iv = g_invdeg[n];
    constexpr int HF4 = T*4;
    for(int k = lane; k < HF4; k += 32){
        int j = half*HF4 + k;
        float4 a4 = A4[j], b4 = B4[j];
        a4.x = (a4.x + b4.x)*iv;
        a4.y = (a4.y + b4.y)*iv;
        a4.z = (a4.z + b4.z)*iv;
        a4.w = (a4.w + b4.w)*iv;
        A4[j] = a4;
    }
    __syncthreads();

    float Wreg[32];
#pragma unroll
    for(int c = 0; c < 32; c++) Wreg[c] = Ws[c*32+lane];
    float scl = g_affine[lane], bia = g_affine[32+lane];
    float gb  = gcb[lane];
    const float* ao = g_acc + n*(T*32) + lane;
    const float* xo = xold + (n*TIN + (TIN-T))*32 + lane;
    float* xn = xnew + n*(T*32) + lane;
    float sum = 0.f, sq = 0.f;
    constexpr int TH = (T+1)/2;
    if(half == 0) epi_fin<T, TIN, TH, 0>(A, Wreg, ao, xo, xn, scl, bia, gb, sum, sq);
    else          epi_fin<T, TIN, T-TH, TH>(A, Wreg, ao, xo, xn, scl, bia, gb, sum, sq);

    rs[tid] = sum; rq[tid] = sq;
    __syncthreads();
    if(tid < 32){
        float ts = 0.f, tq = 0.f;
#pragma unroll
        for(int w = 0; w < 2*NPN; w++){ ts += rs[w*32+tid]; tq += rq[w*32+tid]; }
        int sh = (blockIdx.x & 31)*64;
        atomicAdd(&g_statsS[sh+tid],    (double)ts);
        atomicAdd(&g_statsS[sh+32+tid], (double)tq);
    }
    if(tid == 0){
        __threadfence();
        int d = atomicAdd(&g_done, 1);
        isLast = (d == (int)gridDim.x - 1) ? 1 : 0;
    }
    __syncthreads();
    if(isLast){
        __threadfence();
        if(tid < 32){
            double S = 0.0, Q = 0.0;
            for(int k = 0; k < 32; k++){ S += g_statsS[k*64+tid]; Q += g_statsS[k*64+32+tid]; }
            double mu  = S*(double)invCnt;
            double var = Q*(double)invCnt - mu*mu;
            if(var < 0.0) var = 0.0;
            float scale = bng[tid] * rsqrtf((float)var + 1e-5f);
            g_affine[tid]    = scale;
            g_affine[32+tid] = bnb[tid] - (float)mu*scale;
        }
        __syncthreads();
        for(int j = tid; j < 2048; j += 64*NPN) g_statsS[j] = 0.0;
        if(tid == 0) g_done = 0;
    }
}

// ---------------- head ----------------
__global__ void __launch_bounds__(256) k_head(
    const float* __restrict__ sw_g, const float* __restrict__ sb_g,
    const float* __restrict__ w1, const float* __restrict__ b1,
    const float* __restrict__ w2, const float* __restrict__ b2,
    float* __restrict__ out)
{
    extern __shared__ float sm[];
    float* hlsT    = sm;            // 5120
    float* skipacc = sm + 5120;     // 4096
    float* wbuf    = sm + 9216;     // 8224
    float* y1s     = sm + 17440;    // 8192
    int tid = threadIdx.x;
    int n0 = blockIdx.x*16;

    for(int j = tid; j < 8*16*32; j += 256){
        int c = j & 31, m = (j>>5) & 15, l = j>>9;
        hlsT[(l*32+c)*20 + m] = g_hl[l*(N_NODES*32) + (n0+m)*32 + c];
    }
    float a[16];
    {
        float bs = 0.f;
        for(int l = 0; l < 8; l++) bs += sb_g[l*256+tid];
#pragma unroll
        for(int m = 0; m < 16; m++) a[m] = bs;
    }
    for(int l = 0; l < 8; l++){
        __syncthreads();
        for(int j = tid; j < 8192; j += 256){
            int c = j & 31, O = j >> 5;
            wbuf[c*257+O] = sw_g[l*8192 + O*32 + c];
        }
        __syncthreads();
#pragma unroll 4
        for(int c = 0; c < 32; c++){
            float w = wbuf[c*257+tid];
            const float4* hp = (const float4*)(hlsT + (l*32+c)*20);
#pragma unroll
            for(int m4 = 0; m4 < 4; m4++){
                float4 h4 = hp[m4];
                a[m4*4+0] += h4.x*w; a[m4*4+1] += h4.y*w;
                a[m4*4+2] += h4.z*w; a[m4*4+3] += h4.w*w;
            }
        }
    }
    __syncthreads();
#pragma unroll
    for(int m = 0; m < 16; m++) skipacc[m*256+tid] = fmaxf(a[m], 0.f);
    __syncthreads();

    const float4* sa = (const float4*)skipacc;
    for(int oo = 0; oo < 2; oo++){
        int o = oo*256 + tid;
        float acc[16];
#pragma unroll
        for(int m = 0; m < 16; m++) acc[m] = 0.f;
        const float4* wr = (const float4*)(w1 + o*256);
        for(int c4 = 0; c4 < 64; c4++){
            float4 w = wr[c4];
#pragma unroll
            for(int m = 0; m < 16; m++){
                float4 s = sa[m*64 + c4];
                acc[m] += w.x*s.x + w.y*s.y + w.z*s.z + w.w*s.w;
            }
        }
        float bb = b1[o];
#pragma unroll
        for(int m = 0; m < 16; m++) y1s[m*512+o] = fmaxf(acc[m] + bb, 0.f);
    }
    __syncthreads();

    for(int idx = tid; idx < 16*24; idx += 256){
        int m = idx/24, o = idx - 24*m;
        float acc = b2[o];
        const float4* wp = (const float4*)(w2 + o*512);
        const float4* yp = (const float4*)(y1s + m*512);
        for(int c4 = 0; c4 < 128; c4++){
            float4 ww = wp[c4], yy = yp[c4];
            acc += ww.x*yy.x + ww.y*yy.y + ww.z*yy.z + ww.w*yy.w;
        }
        out[(n0+m)*24 + o] = acc;
    }
}

// ---------------- host ----------------
static inline size_t conv_smem(bool enter, bool last){
    return (size_t)(4096 + (last ? 0 : 1024) + (enter ? 128 : 0) + NPB*32*20) * 4;
}

extern "C" void kernel_launch(void* const* d_in, const int* in_sizes, int n_in,
                              void* d_out, int out_size)
{
    const float* inputs  = (const float*)d_in[0];
    const int*   esrc    = (const int*)  d_in[1];
    const int*   edst    = (const int*)  d_in[2];
    const float* enter_w = (const float*)d_in[3];
    const float* enter_b = (const float*)d_in[4];
    const float* filt_w  = (const float*)d_in[5];
    const float* filt_b  = (const float*)d_in[6];
    const float* gate_w  = (const float*)d_in[7];
    const float* gate_b  = (const float*)d_in[8];
    const float* gc_w    = (const float*)d_in[9];
    const float* gc_b    = (const float*)d_in[10];
    const float* skip_w  = (const float*)d_in[11];
    const float* skip_b  = (const float*)d_in[12];
    const float* bn_g    = (const float*)d_in[13];
    const float* bn_b    = (const float*)d_in[14];
    const float* out1_w  = (const float*)d_in[15];
    const float* out1_b  = (const float*)d_in[16];
    const float* out2_w  = (const float*)d_in[17];
    const float* out2_b  = (const float*)d_in[18];
    float* out = (float*)d_out;

    static int head_attr_set = 0;
    if(!head_attr_set){
        cudaFuncSetAttribute(k_head, cudaFuncAttributeMaxDynamicSharedMemorySize, 25632*4);
        head_attr_set = 1;
    }

    float *xA, *xB, *hl;
    __half *pA, *pB, *hh;
    cudaGetSymbolAddress((void**)&xA, g_xA);
    cudaGetSymbolAddress((void**)&xB, g_xB);
    cudaGetSymbolAddress((void**)&pA, g_pA);
    cudaGetSymbolAddress((void**)&pB, g_pB);
    cudaGetSymbolAddress((void**)&hh, g_h);
    cudaGetSymbolAddress((void**)&hl, g_hl);

    k_hist<<<(N_EDGES+255)/256, 256>>>(edst);
    k_scan<<<1, 1024>>>();
    k_fill<<<(N_EDGES+255)/256, 256>>>(esrc, edst);

    dim3 cb(32, NPB);
    const int GC = N_NODES/NPB;      // 2500
    const int GP = N_NODES/NPN;      // 5000

    // layer 0 (enter fused)
    k_conv<13,1,true,false><<<GC, cb, conv_smem(true,false)>>>(
        inputs, enter_w, enter_b,
        filt_w + 0*2048, filt_b + 0*32, gate_w + 0*2048, gate_b + 0*32,
        gc_w + 0*4096, hl + 0*N_NODES*32, xA);
    k_prop<12><<<GP, 64*NPN>>>(hh, pA, gc_w + (0*4+1)*1024);
    k_prop<12><<<GP, 64*NPN>>>(pA, pB, gc_w + (0*4+2)*1024);
    k_propfin<12,13><<<GP, 64*NPN>>>(pB, gc_w + (0*4+3)*1024, xA, xB,
        gc_b + 0*32, bn_g + 0*32, bn_b + 0*32, 1.f/((float)N_NODES*12.f));

#define LAYER(l, TIN, DD, XIN, XNEW)                                                        \
    {                                                                                       \
        const int t = (TIN) - (DD);                                                         \
        k_conv<TIN, DD, false, false><<<GC, cb, conv_smem(false,false)>>>(                  \
            XIN, 0, 0,                                                                      \
            filt_w + (l)*2048, filt_b + (l)*32, gate_w + (l)*2048, gate_b + (l)*32,         \
            gc_w + (l)*4096, hl + (l)*N_NODES*32, 0);                                       \
        k_prop<(TIN)-(DD)><<<GP, 64*NPN>>>(hh, pA, gc_w + ((l)*4+1)*1024);                  \
        k_prop<(TIN)-(DD)><<<GP, 64*NPN>>>(pA, pB, gc_w + ((l)*4+2)*1024);                  \
        k_propfin<(TIN)-(DD), TIN><<<GP, 64*NPN>>>(pB, gc_w + ((l)*4+3)*1024, XIN, XNEW,    \
            gc_b + (l)*32, bn_g + (l)*32, bn_b + (l)*32, 1.f/((float)N_NODES*(float)t));    \
    }

    LAYER(1, 12, 2, xB, xA)
    LAYER(2, 10, 1, xA, xB)
    LAYER(3,  9, 2, xB, xA)
    LAYER(4,  7, 1, xA, xB)
    LAYER(5,  6, 2, xB, xA)
    LAYER(6,  4, 1, xA, xB)
#undef LAYER

    // layer 7: conv + hl only
    k_conv<3,2,false,true><<<GC, cb, conv_smem(false,true)>>>(
        xB, 0, 0,
        filt_w + 7*2048, filt_b + 7*32, gate_w + 7*2048, gate_b + 7*32,
        gc_w, hl + 7*N_NODES*32, 0);

    k_head<<<N_NODES/16, 256, 25632*4>>>(skip_w, skip_b, out1_w, out1_b, out2_w, out2_b, out);
}

// round 8
// speedup vs baseline: 1.1248x; 1.1248x over previous
#include <cuda_runtime.h>
#include <cuda_fp16.h>
#include <math.h>

#define N_NODES 20000
#define N_EDGES 320000
#define NPB 8
#define PW 4      // warps (nodes) per prop block

// ---------------- device scratch ----------------
__device__ float  g_xA[N_NODES*13*32];
__device__ float  g_xB[N_NODES*13*32];
__device__ __half g_h [N_NODES*12*32];
__device__ float  g_acc[N_NODES*12*32];
__device__ __half g_pA[N_NODES*12*32];
__device__ __half g_pB[N_NODES*12*32];
__device__ float  g_hl[8*N_NODES*32];
__device__ int    g_rowptr[N_NODES+1];
__device__ int    g_curs[N_NODES];
__device__ int    g_cnt[N_NODES];
__device__ float  g_invdeg[N_NODES];
__device__ int    g_col[N_EDGES];
__device__ double g_statsS[32*64];
__device__ float  g_affine[64];
__device__ int    g_done;

__device__ __forceinline__ __half2 H2(unsigned int u){ return *reinterpret_cast<__half2*>(&u); }
__device__ __forceinline__ unsigned int U2(__half2 h){ return *reinterpret_cast<unsigned int*>(&h); }

// ---------------- setup ----------------
__global__ void k_hist(const int* __restrict__ dst){
    int i = blockIdx.x*256 + threadIdx.x;
    if(i < 64) g_affine[i] = (i < 32) ? 1.f : 0.f;
    if(i < N_EDGES) atomicAdd(&g_cnt[dst[i]], 1);
}

__global__ void k_scan(){
    const int CH = 20;
    int tid = threadIdx.x;
    int b0 = tid*CH; if(b0 > N_NODES) b0 = N_NODES;
    int b1 = b0 + CH; if(b1 > N_NODES) b1 = N_NODES;
    int sum = 0;
    for(int i = b0; i < b1; i++) sum += g_cnt[i];
    int lane = tid & 31, w = tid >> 5;
    int v = sum;
#pragma unroll
    for(int o = 1; o < 32; o <<= 1){
        int t = __shfl_up_sync(0xffffffffu, v, o);
        if(lane >= o) v += t;
    }
    __shared__ int wsum[32];
    if(lane == 31) wsum[w] = v;
    __syncthreads();
    if(w == 0){
        int x = wsum[lane];
#pragma unroll
        for(int o = 1; o < 32; o <<= 1){
            int t = __shfl_up_sync(0xffffffffu, x, o);
            if(lane >= o) x += t;
        }
        wsum[lane] = x;
    }
    __syncthreads();
    int pre = v - sum + ((w > 0) ? wsum[w-1] : 0);
    int run = pre;
    for(int i = b0; i < b1; i++){
        int c = g_cnt[i];
        g_curs[i] = run;
        run += c;
        g_rowptr[i+1] = run;
        g_invdeg[i] = 1.f/(float)(c > 0 ? c : 1);
        g_cnt[i] = 0;
    }
    if(tid == 0) g_rowptr[0] = 0;
}

// ---------------- conv body (flat 256 threads; 8 nodes) ----------------
template<int TIN, int D, bool ENTER, bool LAST>
__device__ __forceinline__ void conv_body(
    int n0, float* sm,
    const float* __restrict__ xin,
    const float* __restrict__ ew, const float* __restrict__ eb,
    const float* __restrict__ fw_g, const float* __restrict__ fb_g,
    const float* __restrict__ gw_g, const float* __restrict__ gb_g,
    const float* __restrict__ w0_g,
    float* __restrict__ hl_out, float* __restrict__ xsave)
{
    constexpr int TOUT = TIN - D;
    constexpr int NQ   = (TIN + 3)/4;
    constexpr int TP   = 20;
    float* wq  = sm;
    float* w0  = sm + 4096;
    float* ews = sm + 4096 + (LAST ? 0 : 1024);
    float* xs  = ews + (ENTER ? 128 : 0);

    int tid = threadIdx.x;
    int tx = tid & 31, ty = tid >> 5;
    for(int j = tid; j < 1024; j += 256){
        int o = j & 31, i = j >> 5;
        float4 v;
        v.x = fw_g[(o*32+i)*2+0];
        v.y = fw_g[(o*32+i)*2+1];
        v.z = gw_g[(o*32+i)*2+0];
        v.w = gw_g[(o*32+i)*2+1];
        ((float4*)wq)[j] = v;
    }
    if(!LAST) for(int j = tid; j < 1024; j += 256) w0[j] = w0_g[j];
    if(ENTER){
        if(tid < 96) ews[tid] = ew[tid];
        if(tid < 32) ews[96+tid] = eb[tid];
    }
    __syncthreads();

    int n = n0 + ty;
    float* xrow = xs + ty*(32*TP);
    if(ENTER){
        const float* ip = xin + n*(TIN*3);
        float we0 = ews[tx*3+0], we1 = ews[tx*3+1], we2 = ews[tx*3+2], be = ews[96+tx];
#pragma unroll
        for(int tt = 0; tt < TIN; tt++){
            float v = be + we0*ip[tt*3+0] + we1*ip[tt*3+1] + we2*ip[tt*3+2];
            xrow[tx*TP+tt] = v;
            xsave[(n*TIN+tt)*32+tx] = v;
        }
    } else {
        float scl = g_affine[tx], bia = g_affine[32+tx];
        const float* xp = xin + n*(TIN*32);
#pragma unroll
        for(int tt = 0; tt < TIN; tt++)
            xrow[tx*TP+tt] = xp[tt*32+tx]*scl + bia;
    }
    __syncwarp();

    float f[TOUT], g[TOUT];
    float fb = fb_g[tx], gb = gb_g[tx];
#pragma unroll
    for(int t = 0; t < TOUT; t++){ f[t] = fb; g[t] = gb; }
#pragma unroll
    for(int i = 0; i < 32; i++){
        float4 w4 = ((const float4*)wq)[i*32+tx];
        const float4* xq = (const float4*)(xrow + i*TP);
        float xv[NQ*4];
#pragma unroll
        for(int q = 0; q < NQ; q++){
            float4 t4 = xq[q];
            xv[q*4+0] = t4.x; xv[q*4+1] = t4.y; xv[q*4+2] = t4.z; xv[q*4+3] = t4.w;
        }
#pragma unroll
        for(int tt = 0; tt < TIN; tt++){
            float x = xv[tt];
            if(tt < TOUT){ f[tt]   += w4.x*x; g[tt]   += w4.z*x; }
            if(tt >= D)  { f[tt-D] += w4.y*x; g[tt-D] += w4.w*x; }
        }
    }
    __syncwarp();

    if(!LAST){
        float hlast = 0.f;
#pragma unroll
        for(int t = 0; t < TOUT; t++){
            float h = tanhf(f[t]) * (1.f/(1.f + expf(-g[t])));
            xrow[tx*TP+t] = h;
            g_h[(n*TOUT+t)*32+tx] = __float2half_rn(h);
            if(t == TOUT-1) hlast = h;
        }
        hl_out[n*32+tx] = hlast;
        __syncwarp();

        float u[TOUT];
#pragma unroll
        for(int t = 0; t < TOUT; t++) u[t] = 0.f;
#pragma unroll
        for(int c = 0; c < 32; c++){
            float w = w0[c*32+tx];
            const float4* hq = (const float4*)(xrow + c*TP);
#pragma unroll
            for(int q = 0; q < NQ; q++){
                if(q*4 < TOUT){
                    float4 hv = hq[q];
                    u[q*4+0] += hv.x*w;
                    if(q*4+1 < TOUT) u[q*4+1] += hv.y*w;
                    if(q*4+2 < TOUT) u[q*4+2] += hv.z*w;
                    if(q*4+3 < TOUT) u[q*4+3] += hv.w*w;
                }
            }
        }
#pragma unroll
        for(int t = 0; t < TOUT; t++) g_acc[(n*TOUT+t)*32+tx] = u[t];
    } else {
        float h = tanhf(f[TOUT-1]) * (1.f/(1.f + expf(-g[TOUT-1])));
        hl_out[n*32+tx] = h;
    }
}

template<int TIN, int D, bool ENTER, bool LAST>
__global__ void __launch_bounds__(256) k_conv(
    const float* __restrict__ xin,
    const float* __restrict__ ew, const float* __restrict__ eb,
    const float* __restrict__ fw_g, const float* __restrict__ fb_g,
    const float* __restrict__ gw_g, const float* __restrict__ gb_g,
    const float* __restrict__ w0_g,
    float* __restrict__ hl_out, float* __restrict__ xsave)
{
    extern __shared__ float sm[];
    conv_body<TIN,D,ENTER,LAST>(blockIdx.x*NPB, sm, xin, ew, eb,
        fw_g, fb_g, gw_g, gb_g, w0_g, hl_out, xsave);
}

// fused: blocks [0,1250) do edge fill; blocks [1250, 3750) do conv layer 0
__global__ void __launch_bounds__(256) k_fillconv(
    const int* __restrict__ src, const int* __restrict__ dst,
    const float* __restrict__ xin,
    const float* __restrict__ ew, const float* __restrict__ eb,
    const float* __restrict__ fw_g, const float* __restrict__ fb_g,
    const float* __restrict__ gw_g, const float* __restrict__ gb_g,
    const float* __restrict__ w0_g,
    float* __restrict__ hl_out, float* __restrict__ xsave)
{
    extern __shared__ float sm[];
    if(blockIdx.x < 1250){
        int e = blockIdx.x*256 + threadIdx.x;
        if(e < N_EDGES){
            int pos = atomicAdd(&g_curs[dst[e]], 1);
            g_col[pos] = src[e];
        }
    } else {
        conv_body<13,1,true,false>((blockIdx.x-1250)*NPB, sm, xin, ew, eb,
            fw_g, fb_g, gw_g, gb_g, w0_g, hl_out, xsave);
    }
}

// ---------------- fp16 gather core: one warp per node, contiguous edges ----------------
template<int T>
__device__ __forceinline__ void gather_row_h(const uint4* __restrict__ in,
                                             int n, int lane, float* acc)
{
    constexpr int R  = T*4;
    constexpr int NV = (R + 31)/32;
    constexpr int EG = (NV == 1) ? 8 : 4;
#pragma unroll
    for(int k = 0; k < NV*8; k++) acc[k] = 0.f;
    int beg = g_rowptr[n], end = g_rowptr[n+1];
    int e = beg;
    for(; e + EG <= end; e += EG){
        int s[EG];
#pragma unroll
        for(int j = 0; j < EG; j++) s[j] = g_col[e+j];
        uint4 q[EG*NV];
#pragma unroll
        for(int j = 0; j < EG; j++){
#pragma unroll
            for(int v = 0; v < NV; v++){
                int idx = v*32 + lane;
                if(idx < R) q[j*NV+v] = in[s[j]*R + idx];
            }
        }
#pragma unroll
        for(int v = 0; v < NV; v++){
            int idx = v*32 + lane;
            if(idx < R){
                __half2 tx_[EG], ty_[EG], tz_[EG], tw_[EG];
#pragma unroll
                for(int j = 0; j < EG; j++){
                    tx_[j] = H2(q[j*NV+v].x); ty_[j] = H2(q[j*NV+v].y);
                    tz_[j] = H2(q[j*NV+v].z); tw_[j] = H2(q[j*NV+v].w);
                }
#pragma unroll
                for(int st = 1; st < EG; st <<= 1){
#pragma unroll
                    for(int j = 0; j < EG; j += 2*st){
                        tx_[j] = __hadd2(tx_[j], tx_[j+st]);
                        ty_[j] = __hadd2(ty_[j], ty_[j+st]);
                        tz_[j] = __hadd2(tz_[j], tz_[j+st]);
                        tw_[j] = __hadd2(tw_[j], tw_[j+st]);
                    }
                }
                float2 f;
                f = __half22float2(tx_[0]); acc[v*8+0] += f.x; acc[v*8+1] += f.y;
                f = __half22float2(ty_[0]); acc[v*8+2] += f.x; acc[v*8+3] += f.y;
                f = __half22float2(tz_[0]); acc[v*8+4] += f.x; acc[v*8+5] += f.y;
                f = __half22float2(tw_[0]); acc[v*8+6] += f.x; acc[v*8+7] += f.y;
            }
        }
    }
    for(; e < end; e++){
        int s0 = g_col[e];
        const uint4* r0 = in + s0*R;
#pragma unroll
        for(int v = 0; v < NV; v++){
            int idx = v*32 + lane;
            if(idx < R){
                uint4 q = r0[idx];
                float2 f;
                f = __half22float2(H2(q.x)); acc[v*8+0] += f.x; acc[v*8+1] += f.y;
                f = __half22float2(H2(q.y)); acc[v*8+2] += f.x; acc[v*8+3] += f.y;
                f = __half22float2(H2(q.z)); acc[v*8+4] += f.x; acc[v*8+5] += f.y;
                f = __half22float2(H2(q.w)); acc[v*8+6] += f.x; acc[v*8+7] += f.y;
            }
        }
    }
    float iv = g_invdeg[n];
#pragma unroll
    for(int k = 0; k < NV*8; k++) acc[k] *= iv;
}

template<int T>
__device__ __forceinline__ void acc_to_tile(const float* acc, float* tile, int lane){
    constexpr int R  = T*4;
    constexpr int NV = (R + 31)/32;
#pragma unroll
    for(int v = 0; v < NV; v++){
        int idx = v*32 + lane;
        if(idx < R){
            int t = idx >> 2, c0 = (idx & 3) << 3;
            float4* tp = (float4*)(tile + t*32 + c0);
            tp[0] = make_float4(acc[v*8+0], acc[v*8+1], acc[v*8+2], acc[v*8+3]);
            tp[1] = make_float4(acc[v*8+4], acc[v*8+5], acc[v*8+6], acc[v*8+7]);
        }
    }
}

// ---------------- diffusion hop: cur = A*in ; g_acc += cur @ Wk ----------------
template<int T>
__global__ void __launch_bounds__(32*PW, 8) k_prop(
    const __half* __restrict__ in, __half* __restrict__ curout,
    const float* __restrict__ Wk)
{
    constexpr int R  = T*4;
    constexpr int NV = (R + 31)/32;
    __shared__ float Ws[1024];
    __shared__ __align__(16) float smS[PW*12*32];
    int tid = threadIdx.x, lane = tid & 31, wid = tid >> 5;
    for(int j = tid; j < 1024; j += 32*PW) Ws[j] = Wk[j];
    __syncthreads();

    int n = blockIdx.x*PW + wid;
    float acc[NV*8];
    gather_row_h<T>((const uint4*)in, n, lane, acc);

    float* tile = smS + wid*(T*32);
    acc_to_tile<T>(acc, tile, lane);
    uint4* cp = (uint4*)curout + n*R;
#pragma unroll
    for(int v = 0; v < NV; v++){
        int idx = v*32 + lane;
        if(idx < R){
            uint4 q;
            q.x = U2(__floats2half2_rn(acc[v*8+0], acc[v*8+1]));
            q.y = U2(__floats2half2_rn(acc[v*8+2], acc[v*8+3]));
            q.z = U2(__floats2half2_rn(acc[v*8+4], acc[v*8+5]));
            q.w = U2(__floats2half2_rn(acc[v*8+6], acc[v*8+7]));
            cp[idx] = q;
        }
    }
    __syncwarp();

    float a[T];
#pragma unroll
    for(int t = 0; t < T; t++) a[t] = 0.f;
    const float4* tp = (const float4*)tile;
#pragma unroll
    for(int c4 = 0; c4 < 8; c4++){
        float w0 = Ws[(c4*4+0)*32+lane];
        float w1 = Ws[(c4*4+1)*32+lane];
        float w2 = Ws[(c4*4+2)*32+lane];
        float w3 = Ws[(c4*4+3)*32+lane];
#pragma unroll
        for(int t = 0; t < T; t++){
            float4 sv = tp[t*8+c4];
            a[t] += sv.x*w0 + sv.y*w1 + sv.z*w2 + sv.w*w3;
        }
    }
    float* ap = g_acc + n*(T*32) + lane;
#pragma unroll
    for(int t = 0; t < T; t++) ap[t*32] += a[t];
}

// ---------------- hop 3 fused with finalize ----------------
template<int T, int TIN>
__global__ void __launch_bounds__(32*PW, 8) k_propfin(
    const __half* __restrict__ in, const float* __restrict__ Wk,
    const float* __restrict__ xold, float* __restrict__ xnew,
    const float* __restrict__ gcb,
    const float* __restrict__ bng, const float* __restrict__ bnb, float invCnt)
{
    constexpr int R  = T*4;
    constexpr int NV = (R + 31)/32;
    __shared__ float Ws[1024];
    __shared__ __align__(16) float smS[PW*12*32];
    __shared__ float rs[32*PW], rq[32*PW];
    __shared__ int isLast;
    int tid = threadIdx.x, lane = tid & 31, wid = tid >> 5;
    for(int j = tid; j < 1024; j += 32*PW) Ws[j] = Wk[j];
    __syncthreads();

    int n = blockIdx.x*PW + wid;
    float acc[NV*8];
    gather_row_h<T>((const uint4*)in, n, lane, acc);
    float* tile = smS + wid*(T*32);
    acc_to_tile<T>(acc, tile, lane);
    __syncwarp();

    float a[T];
#pragma unroll
    for(int t = 0; t < T; t++) a[t] = 0.f;
    const float4* tp = (const float4*)tile;
#pragma unroll
    for(int c4 = 0; c4 < 8; c4++){
        float w0 = Ws[(c4*4+0)*32+lane];
        float w1 = Ws[(c4*4+1)*32+lane];
        float w2 = Ws[(c4*4+2)*32+lane];
        float w3 = Ws[(c4*4+3)*32+lane];
#pragma unroll
        for(int t = 0; t < T; t++){
            float4 sv = tp[t*8+c4];
            a[t] += sv.x*w0 + sv.y*w1 + sv.z*w2 + sv.w*w3;
        }
    }
    float scl = g_affine[lane], bia = g_affine[32+lane];
    float gb  = gcb[lane];
    const float* ao = g_acc + n*(T*32) + lane;
    const float* xo = xold + (n*TIN + (TIN-T))*32 + lane;
    float* xn = xnew + n*(T*32) + lane;
    float sum = 0.f, sq = 0.f;
#pragma unroll
    for(int t = 0; t < T; t++){
        float v = a[t] + ao[t*32] + gb + xo[t*32]*scl + bia;
        xn[t*32] = v;
        sum += v; sq += v*v;
    }
    rs[tid] = sum; rq[tid] = sq;
    __syncthreads();
    if(tid < 32){
        float ts = 0.f, tq = 0.f;
#pragma unroll
        for(int w = 0; w < PW; w++){ ts += rs[w*32+tid]; tq += rq[w*32+tid]; }
        int sh = (blockIdx.x & 31)*64;
        atomicAdd(&g_statsS[sh+tid],    (double)ts);
        atomicAdd(&g_statsS[sh+32+tid], (double)tq);
    }
    if(tid == 0){
        __threadfence();
        int d = atomicAdd(&g_done, 1);
        isLast = (d == (int)gridDim.x - 1) ? 1 : 0;
    }
    __syncthreads();
    if(isLast){
        __threadfence();
        if(tid < 32){
            double S = 0.0, Q = 0.0;
            for(int k = 0; k < 32; k++){ S += g_statsS[k*64+tid]; Q += g_statsS[k*64+32+tid]; }
            double mu  = S*(double)invCnt;
            double var = Q*(double)invCnt - mu*mu;
            if(var < 0.0) var = 0.0;
            float scale = bng[tid] * rsqrtf((float)var + 1e-5f);
            g_affine[tid]    = scale;
            g_affine[32+tid] = bnb[tid] - (float)mu*scale;
        }
        __syncthreads();
        for(int j = tid; j < 2048; j += 32*PW) g_statsS[j] = 0.0;
        if(tid == 0) g_done = 0;
    }
}

// ---------------- head ----------------
__global__ void __launch_bounds__(256) k_head(
    const float* __restrict__ sw_g, const float* __restrict__ sb_g,
    const float* __restrict__ w1, const float* __restrict__ b1,
    const float* __restrict__ w2, const float* __restrict__ b2,
    float* __restrict__ out)
{
    extern __shared__ float sm[];
    float* hlsT    = sm;            // 5120
    float* skipacc = sm + 5120;     // 4096
    float* wbuf    = sm + 9216;     // 8224
    float* y1s     = sm + 17440;    // 8192
    int tid = threadIdx.x;
    int n0 = blockIdx.x*16;

    for(int j = tid; j < 8*16*32; j += 256){
        int c = j & 31, m = (j>>5) & 15, l = j>>9;
        hlsT[(l*32+c)*20 + m] = g_hl[l*(N_NODES*32) + (n0+m)*32 + c];
    }
    float a[16];
    {
        float bs = 0.f;
        for(int l = 0; l < 8; l++) bs += sb_g[l*256+tid];
#pragma unroll
        for(int m = 0; m < 16; m++) a[m] = bs;
    }
    for(int l = 0; l < 8; l++){
        __syncthreads();
        for(int j = tid; j < 8192; j += 256){
            int c = j & 31, O = j >> 5;
            wbuf[c*257+O] = sw_g[l*8192 + O*32 + c];
        }
        __syncthreads();
#pragma unroll 4
        for(int c = 0; c < 32; c++){
            float w = wbuf[c*257+tid];
            const float4* hp = (const float4*)(hlsT + (l*32+c)*20);
#pragma unroll
            for(int m4 = 0; m4 < 4; m4++){
                float4 h4 = hp[m4];
                a[m4*4+0] += h4.x*w; a[m4*4+1] += h4.y*w;
                a[m4*4+2] += h4.z*w; a[m4*4+3] += h4.w*w;
            }
        }
    }
    __syncthreads();
#pragma unroll
    for(int m = 0; m < 16; m++) skipacc[m*256+tid] = fmaxf(a[m], 0.f);
    __syncthreads();

    const float4* sa = (const float4*)skipacc;
    for(int oo = 0; oo < 2; oo++){
        int o = oo*256 + tid;
        float acc[16];
#pragma unroll
        for(int m = 0; m < 16; m++) acc[m] = 0.f;
        const float4* wr = (const float4*)(w1 + o*256);
        for(int c4 = 0; c4 < 64; c4++){
            float4 w = wr[c4];
#pragma unroll
            for(int m = 0; m < 16; m++){
                float4 s = sa[m*64 + c4];
                acc[m] += w.x*s.x + w.y*s.y + w.z*s.z + w.w*s.w;
            }
        }
        float bb = b1[o];
#pragma unroll
        for(int m = 0; m < 16; m++) y1s[m*512+o] = fmaxf(acc[m] + bb, 0.f);
    }
    __syncthreads();

    for(int idx = tid; idx < 16*24; idx += 256){
        int m = idx/24, o = idx - 24*m;
        float acc = b2[o];
        const float4* wp = (const float4*)(w2 + o*512);
        const float4* yp = (const float4*)(y1s + m*512);
        for(int c4 = 0; c4 < 128; c4++){
            float4 ww = wp[c4], yy = yp[c4];
            acc += ww.x*yy.x + ww.y*yy.y + ww.z*yy.z + ww.w*yy.w;
        }
        out[(n0+m)*24 + o] = acc;
    }
}

// ---------------- host ----------------
static inline size_t conv_smem(bool enter, bool last){
    return (size_t)(4096 + (last ? 0 : 1024) + (enter ? 128 : 0) + NPB*32*20) * 4;
}

extern "C" void kernel_launch(void* const* d_in, const int* in_sizes, int n_in,
                              void* d_out, int out_size)
{
    const float* inputs  = (const float*)d_in[0];
    const int*   esrc    = (const int*)  d_in[1];
    const int*   edst    = (const int*)  d_in[2];
    const float* enter_w = (const float*)d_in[3];
    const float* enter_b = (const float*)d_in[4];
    const float* filt_w  = (const float*)d_in[5];
    const float* filt_b  = (const float*)d_in[6];
    const float* gate_w  = (const float*)d_in[7];
    const float* gate_b  = (const float*)d_in[8];
    const float* gc_w    = (const float*)d_in[9];
    const float* gc_b    = (const float*)d_in[10];
    const float* skip_w  = (const float*)d_in[11];
    const float* skip_b  = (const float*)d_in[12];
    const float* bn_g    = (const float*)d_in[13];
    const float* bn_b    = (const float*)d_in[14];
    const float* out1_w  = (const float*)d_in[15];
    const float* out1_b  = (const float*)d_in[16];
    const float* out2_w  = (const float*)d_in[17];
    const float* out2_b  = (const float*)d_in[18];
    float* out = (float*)d_out;

    static int attr_set = 0;
    if(!attr_set){
        cudaFuncSetAttribute(k_head, cudaFuncAttributeMaxDynamicSharedMemorySize, 25632*4);
        attr_set = 1;
    }

    float *xA, *xB, *hl;
    __half *pA, *pB, *hh;
    cudaGetSymbolAddress((void**)&xA, g_xA);
    cudaGetSymbolAddress((void**)&xB, g_xB);
    cudaGetSymbolAddress((void**)&pA, g_pA);
    cudaGetSymbolAddress((void**)&pB, g_pB);
    cudaGetSymbolAddress((void**)&hh, g_h);
    cudaGetSymbolAddress((void**)&hl, g_hl);

    k_hist<<<(N_EDGES+255)/256, 256>>>(edst);
    k_scan<<<1, 1024>>>();

    const int GC = N_NODES/NPB;      // 2500
    const int GP = N_NODES/PW;       // 5000

    // fused: edge fill + conv layer 0 (enter fused)
    k_fillconv<<<1250 + GC, 256, conv_smem(true,false)>>>(
        esrc, edst,
        inputs, enter_w, enter_b,
        filt_w + 0*2048, filt_b + 0*32, gate_w + 0*2048, gate_b + 0*32,
        gc_w + 0*4096, hl + 0*N_NODES*32, xA);
    k_prop<12><<<GP, 32*PW>>>(hh, pA, gc_w + (0*4+1)*1024);
    k_prop<12><<<GP, 32*PW>>>(pA, pB, gc_w + (0*4+2)*1024);
    k_propfin<12,13><<<GP, 32*PW>>>(pB, gc_w + (0*4+3)*1024, xA, xB,
        gc_b + 0*32, bn_g + 0*32, bn_b + 0*32, 1.f/((float)N_NODES*12.f));

#define LAYER(l, TIN, DD, XIN, XNEW)                                                        \
    {                                                                                       \
        const int t = (TIN) - (DD);                                                         \
        k_conv<TIN, DD, false, false><<<GC, 256, conv_smem(false,false)>>>(                 \
            XIN, 0, 0,                                                                      \
            filt_w + (l)*2048, filt_b + (l)*32, gate_w + (l)*2048, gate_b + (l)*32,         \
            gc_w + (l)*4096, hl + (l)*N_NODES*32, 0);                                       \
        k_prop<(TIN)-(DD)><<<GP, 32*PW>>>(hh, pA, gc_w + ((l)*4+1)*1024);                   \
        k_prop<(TIN)-(DD)><<<GP, 32*PW>>>(pA, pB, gc_w + ((l)*4+2)*1024);                   \
        k_propfin<(TIN)-(DD), TIN><<<GP, 32*PW>>>(pB, gc_w + ((l)*4+3)*1024, XIN, XNEW,     \
            gc_b + (l)*32, bn_g + (l)*32, bn_b + (l)*32, 1.f/((float)N_NODES*(float)t));    \
    }

    LAYER(1, 12, 2, xB, xA)
    LAYER(2, 10, 1, xA, xB)
    LAYER(3,  9, 2, xB, xA)
    LAYER(4,  7, 1, xA, xB)
    LAYER(5,  6, 2, xB, xA)
    LAYER(6,  4, 1, xA, xB)
#undef LAYER

    // layer 7: conv + hl only
    k_conv<3,2,false,true><<<GC, 256, conv_smem(false,true)>>>(
        xB, 0, 0,
        filt_w + 7*2048, filt_b + 7*32, gate_w + 7*2048, gate_b + 7*32,
        gc_w, hl + 7*N_NODES*32, 0);

    k_head<<<N_NODES/16, 256, 25632*4>>>(skip_w, skip_b, out1_w, out1_b, out2_w, out2_b, out);
}

// round 9
// speedup vs baseline: 1.2039x; 1.0703x over previous
#include <cuda_runtime.h>
#include <cuda_fp16.h>
#include <math.h>

#define N_NODES 20000
#define N_EDGES 320000
#define NPB 8
#define PW 4      // warps (nodes) per prop block

// ---------------- device scratch ----------------
__device__ float  g_xA[N_NODES*13*32];
__device__ float  g_xB[N_NODES*13*32];
__device__ __half g_h [N_NODES*12*32];
__device__ __half g_pA[N_NODES*12*32];
__device__ __half g_pB[N_NODES*12*32];
__device__ float  g_hl[8*N_NODES*32];
__device__ int    g_rowptr[N_NODES+1];
__device__ int    g_curs[N_NODES];
__device__ int    g_cnt[N_NODES];
__device__ float  g_invdeg[N_NODES];
__device__ int    g_col[N_EDGES];
__device__ double g_statsS[32*64];
__device__ float  g_affine[64];
__device__ int    g_done;

__device__ __forceinline__ __half2 H2(unsigned int u){ return *reinterpret_cast<__half2*>(&u); }
__device__ __forceinline__ unsigned int U2(__half2 h){ return *reinterpret_cast<unsigned int*>(&h); }

// ---------------- setup ----------------
__global__ void k_hist(const int* __restrict__ dst){
    int i = blockIdx.x*256 + threadIdx.x;
    if(i < 64) g_affine[i] = (i < 32) ? 1.f : 0.f;
    if(i < N_EDGES) atomicAdd(&g_cnt[dst[i]], 1);
}

__global__ void k_scan(){
    const int CH = 20;
    int tid = threadIdx.x;
    int b0 = tid*CH; if(b0 > N_NODES) b0 = N_NODES;
    int b1 = b0 + CH; if(b1 > N_NODES) b1 = N_NODES;
    int sum = 0;
    for(int i = b0; i < b1; i++) sum += g_cnt[i];
    int lane = tid & 31, w = tid >> 5;
    int v = sum;
#pragma unroll
    for(int o = 1; o < 32; o <<= 1){
        int t = __shfl_up_sync(0xffffffffu, v, o);
        if(lane >= o) v += t;
    }
    __shared__ int wsum[32];
    if(lane == 31) wsum[w] = v;
    __syncthreads();
    if(w == 0){
        int x = wsum[lane];
#pragma unroll
        for(int o = 1; o < 32; o <<= 1){
            int t = __shfl_up_sync(0xffffffffu, x, o);
            if(lane >= o) x += t;
        }
        wsum[lane] = x;
    }
    __syncthreads();
    int pre = v - sum + ((w > 0) ? wsum[w-1] : 0);
    int run = pre;
    for(int i = b0; i < b1; i++){
        int c = g_cnt[i];
        g_curs[i] = run;
        run += c;
        g_rowptr[i+1] = run;
        g_invdeg[i] = 1.f/(float)(c > 0 ? c : 1);
        g_cnt[i] = 0;
    }
    if(tid == 0) g_rowptr[0] = 0;
}

// ---------------- conv body (flat 256 threads; 8 nodes): gated conv -> h(fp16), hl ----------------
template<int TIN, int D, bool ENTER, bool LAST>
__device__ __forceinline__ void conv_body(
    int n0, float* sm,
    const float* __restrict__ xin,
    const float* __restrict__ ew, const float* __restrict__ eb,
    const float* __restrict__ fw_g, const float* __restrict__ fb_g,
    const float* __restrict__ gw_g, const float* __restrict__ gb_g,
    float* __restrict__ hl_out, float* __restrict__ xsave)
{
    constexpr int TOUT = TIN - D;
    constexpr int NQ   = (TIN + 3)/4;
    constexpr int TP   = 20;
    float* wq  = sm;
    float* ews = sm + 4096;
    float* xs  = ews + (ENTER ? 128 : 0);

    int tid = threadIdx.x;
    int tx = tid & 31, ty = tid >> 5;
    for(int j = tid; j < 1024; j += 256){
        int o = j & 31, i = j >> 5;
        float4 v;
        v.x = fw_g[(o*32+i)*2+0];
        v.y = fw_g[(o*32+i)*2+1];
        v.z = gw_g[(o*32+i)*2+0];
        v.w = gw_g[(o*32+i)*2+1];
        ((float4*)wq)[j] = v;
    }
    if(ENTER){
        if(tid < 96) ews[tid] = ew[tid];
        if(tid < 32) ews[96+tid] = eb[tid];
    }
    __syncthreads();

    int n = n0 + ty;
    float* xrow = xs + ty*(32*TP);
    if(ENTER){
        const float* ip = xin + n*(TIN*3);
        float we0 = ews[tx*3+0], we1 = ews[tx*3+1], we2 = ews[tx*3+2], be = ews[96+tx];
#pragma unroll
        for(int tt = 0; tt < TIN; tt++){
            float v = be + we0*ip[tt*3+0] + we1*ip[tt*3+1] + we2*ip[tt*3+2];
            xrow[tx*TP+tt] = v;
            xsave[(n*TIN+tt)*32+tx] = v;
        }
    } else {
        float scl = g_affine[tx], bia = g_affine[32+tx];
        const float* xp = xin + n*(TIN*32);
#pragma unroll
        for(int tt = 0; tt < TIN; tt++)
            xrow[tx*TP+tt] = xp[tt*32+tx]*scl + bia;
    }
    __syncwarp();

    float f[TOUT], g[TOUT];
    float fb = fb_g[tx], gb = gb_g[tx];
#pragma unroll
    for(int t = 0; t < TOUT; t++){ f[t] = fb; g[t] = gb; }
#pragma unroll
    for(int i = 0; i < 32; i++){
        float4 w4 = ((const float4*)wq)[i*32+tx];
        const float4* xq = (const float4*)(xrow + i*TP);
        float xv[NQ*4];
#pragma unroll
        for(int q = 0; q < NQ; q++){
            float4 t4 = xq[q];
            xv[q*4+0] = t4.x; xv[q*4+1] = t4.y; xv[q*4+2] = t4.z; xv[q*4+3] = t4.w;
        }
#pragma unroll
        for(int tt = 0; tt < TIN; tt++){
            float x = xv[tt];
            if(tt < TOUT){ f[tt]   += w4.x*x; g[tt]   += w4.z*x; }
            if(tt >= D)  { f[tt-D] += w4.y*x; g[tt-D] += w4.w*x; }
        }
    }

    if(!LAST){
        float hlast = 0.f;
#pragma unroll
        for(int t = 0; t < TOUT; t++){
            float h = tanhf(f[t]) * (1.f/(1.f + expf(-g[t])));
            g_h[(n*TOUT+t)*32+tx] = __float2half_rn(h);
            if(t == TOUT-1) hlast = h;
        }
        hl_out[n*32+tx] = hlast;
    } else {
        float h = tanhf(f[TOUT-1]) * (1.f/(1.f + expf(-g[TOUT-1])));
        hl_out[n*32+tx] = h;
    }
}

template<int TIN, int D, bool ENTER, bool LAST>
__global__ void __launch_bounds__(256) k_conv(
    const float* __restrict__ xin,
    const float* __restrict__ ew, const float* __restrict__ eb,
    const float* __restrict__ fw_g, const float* __restrict__ fb_g,
    const float* __restrict__ gw_g, const float* __restrict__ gb_g,
    float* __restrict__ hl_out, float* __restrict__ xsave)
{
    extern __shared__ float sm[];
    conv_body<TIN,D,ENTER,LAST>(blockIdx.x*NPB, sm, xin, ew, eb,
        fw_g, fb_g, gw_g, gb_g, hl_out, xsave);
}

// fused: blocks [0,1250) do edge fill; rest do conv layer 0
__global__ void __launch_bounds__(256) k_fillconv(
    const int* __restrict__ src, const int* __restrict__ dst,
    const float* __restrict__ xin,
    const float* __restrict__ ew, const float* __restrict__ eb,
    const float* __restrict__ fw_g, const float* __restrict__ fb_g,
    const float* __restrict__ gw_g, const float* __restrict__ gb_g,
    float* __restrict__ hl_out, float* __restrict__ xsave)
{
    extern __shared__ float sm[];
    if(blockIdx.x < 1250){
        int e = blockIdx.x*256 + threadIdx.x;
        if(e < N_EDGES){
            int pos = atomicAdd(&g_curs[dst[e]], 1);
            g_col[pos] = src[e];
        }
    } else {
        conv_body<13,1,true,false>((blockIdx.x-1250)*NPB, sm, xin, ew, eb,
            fw_g, fb_g, gw_g, gb_g, hl_out, xsave);
    }
}

// ---------------- fp16 gather core: one warp per node, contiguous edges ----------------
template<int T>
__device__ __forceinline__ void gather_row_h(const uint4* __restrict__ in,
                                             int n, int lane, float* acc)
{
    constexpr int R  = T*4;
    constexpr int NV = (R + 31)/32;
    constexpr int EG = (NV == 1) ? 8 : 4;
#pragma unroll
    for(int k = 0; k < NV*8; k++) acc[k] = 0.f;
    int beg = g_rowptr[n], end = g_rowptr[n+1];
    int e = beg;
    for(; e + EG <= end; e += EG){
        int s[EG];
#pragma unroll
        for(int j = 0; j < EG; j++) s[j] = g_col[e+j];
        uint4 q[EG*NV];
#pragma unroll
        for(int j = 0; j < EG; j++){
#pragma unroll
            for(int v = 0; v < NV; v++){
                int idx = v*32 + lane;
                if(idx < R) q[j*NV+v] = in[s[j]*R + idx];
            }
        }
#pragma unroll
        for(int v = 0; v < NV; v++){
            int idx = v*32 + lane;
            if(idx < R){
                __half2 tx_[EG], ty_[EG], tz_[EG], tw_[EG];
#pragma unroll
                for(int j = 0; j < EG; j++){
                    tx_[j] = H2(q[j*NV+v].x); ty_[j] = H2(q[j*NV+v].y);
                    tz_[j] = H2(q[j*NV+v].z); tw_[j] = H2(q[j*NV+v].w);
                }
#pragma unroll
                for(int st = 1; st < EG; st <<= 1){
#pragma unroll
                    for(int j = 0; j < EG; j += 2*st){
                        tx_[j] = __hadd2(tx_[j], tx_[j+st]);
                        ty_[j] = __hadd2(ty_[j], ty_[j+st]);
                        tz_[j] = __hadd2(tz_[j], tz_[j+st]);
                        tw_[j] = __hadd2(tw_[j], tw_[j+st]);
                    }
                }
                float2 f;
                f = __half22float2(tx_[0]); acc[v*8+0] += f.x; acc[v*8+1] += f.y;
                f = __half22float2(ty_[0]); acc[v*8+2] += f.x; acc[v*8+3] += f.y;
                f = __half22float2(tz_[0]); acc[v*8+4] += f.x; acc[v*8+5] += f.y;
                f = __half22float2(tw_[0]); acc[v*8+6] += f.x; acc[v*8+7] += f.y;
            }
        }
    }
    for(; e < end; e++){
        int s0 = g_col[e];
        const uint4* r0 = in + s0*R;
#pragma unroll
        for(int v = 0; v < NV; v++){
            int idx = v*32 + lane;
            if(idx < R){
                uint4 q = r0[idx];
                float2 f;
                f = __half22float2(H2(q.x)); acc[v*8+0] += f.x; acc[v*8+1] += f.y;
                f = __half22float2(H2(q.y)); acc[v*8+2] += f.x; acc[v*8+3] += f.y;
                f = __half22float2(H2(q.z)); acc[v*8+4] += f.x; acc[v*8+5] += f.y;
                f = __half22float2(H2(q.w)); acc[v*8+6] += f.x; acc[v*8+7] += f.y;
            }
        }
    }
    float iv = g_invdeg[n];
#pragma unroll
    for(int k = 0; k < NV*8; k++) acc[k] *= iv;
}

// scatter gathered fp32 values into smem tile (t-major, 32 ch)
template<int T>
__device__ __forceinline__ void acc_to_tile(const float* acc, float* tile, int lane){
    constexpr int R  = T*4;
    constexpr int NV = (R + 31)/32;
#pragma unroll
    for(int v = 0; v < NV; v++){
        int idx = v*32 + lane;
        if(idx < R){
            int t = idx >> 2, c0 = (idx & 3) << 3;
            float4* tp = (float4*)(tile + t*32 + c0);
            tp[0] = make_float4(acc[v*8+0], acc[v*8+1], acc[v*8+2], acc[v*8+3]);
            tp[1] = make_float4(acc[v*8+4], acc[v*8+5], acc[v*8+6], acc[v*8+7]);
        }
    }
}

// load an fp16 row (own node, coalesced) into the fp32 smem tile
template<int T>
__device__ __forceinline__ void row_to_tile(const __half* __restrict__ row,
                                            float* tile, int lane){
    constexpr int R  = T*4;
    constexpr int NV = (R + 31)/32;
    const uint4* r4 = (const uint4*)row;
#pragma unroll
    for(int v = 0; v < NV; v++){
        int idx = v*32 + lane;
        if(idx < R){
            uint4 q = r4[idx];
            int t = idx >> 2, c0 = (idx & 3) << 3;
            float4* tp = (float4*)(tile + t*32 + c0);
            float2 fx = __half22float2(H2(q.x));
            float2 fy = __half22float2(H2(q.y));
            float2 fz = __half22float2(H2(q.z));
            float2 fw = __half22float2(H2(q.w));
            tp[0] = make_float4(fx.x, fx.y, fy.x, fy.y);
            tp[1] = make_float4(fz.x, fz.y, fw.x, fw.y);
        }
    }
}

// GEMM: a[t] += sum_c tile[t][c] * W[c][lane]
template<int T>
__device__ __forceinline__ void gemm_acc(const float* tile, const float* Ws,
                                         int lane, float* a){
    const float4* tp = (const float4*)tile;
#pragma unroll
    for(int c4 = 0; c4 < 8; c4++){
        float w0 = Ws[(c4*4+0)*32+lane];
        float w1 = Ws[(c4*4+1)*32+lane];
        float w2 = Ws[(c4*4+2)*32+lane];
        float w3 = Ws[(c4*4+3)*32+lane];
#pragma unroll
        for(int t = 0; t < T; t++){
            float4 sv = tp[t*8+c4];
            a[t] += sv.x*w0 + sv.y*w1 + sv.z*w2 + sv.w*w3;
        }
    }
}

// ---------------- pure diffusion hop: out = A*in (fp16 -> fp16) ----------------
template<int T>
__global__ void __launch_bounds__(128) k_hop(
    const __half* __restrict__ in, __half* __restrict__ out)
{
    constexpr int R  = T*4;
    constexpr int NV = (R + 31)/32;
    int tid = threadIdx.x, lane = tid & 31, wid = tid >> 5;
    int n = blockIdx.x*PW + wid;
    float acc[NV*8];
    gather_row_h<T>((const uint4*)in, n, lane, acc);
    uint4* cp = (uint4*)out + n*R;
#pragma unroll
    for(int v = 0; v < NV; v++){
        int idx = v*32 + lane;
        if(idx < R){
            uint4 q;
            q.x = U2(__floats2half2_rn(acc[v*8+0], acc[v*8+1]));
            q.y = U2(__floats2half2_rn(acc[v*8+2], acc[v*8+3]));
            q.z = U2(__floats2half2_rn(acc[v*8+4], acc[v*8+5]));
            q.w = U2(__floats2half2_rn(acc[v*8+6], acc[v*8+7]));
            cp[idx] = q;
        }
    }
}

// ---------------- propfin: p3 = A*p2 ; x = h@W0+p1@W1+p2@W2+p3@W3 + gcb + affine(xold); BN ----------------
template<int T, int TIN>
__global__ void __launch_bounds__(128) k_propfin(
    const __half* __restrict__ in,        // p2
    const __half* __restrict__ p1,
    const float* __restrict__ Wk4,        // 4x 32x32
    const float* __restrict__ xold, float* __restrict__ xnew,
    const float* __restrict__ gcb,
    const float* __restrict__ bng, const float* __restrict__ bnb, float invCnt)
{
    constexpr int R  = T*4;
    constexpr int NV = (R + 31)/32;
    __shared__ float Ws[4096];
    __shared__ __align__(16) float smS[PW*12*32];
    __shared__ float rs[32*PW], rq[32*PW];
    __shared__ int isLast;
    int tid = threadIdx.x, lane = tid & 31, wid = tid >> 5;
    for(int j = tid; j < 4096; j += 128) Ws[j] = Wk4[j];
    __syncthreads();

    int n = blockIdx.x*PW + wid;
    float acc[NV*8];
    gather_row_h<T>((const uint4*)in, n, lane, acc);   // p3

    float a[T];
#pragma unroll
    for(int t = 0; t < T; t++) a[t] = 0.f;
    float* tile = smS + wid*(T*32);

    row_to_tile<T>(g_h + n*(T*32), tile, lane);  __syncwarp();
    gemm_acc<T>(tile, Ws,        lane, a);       __syncwarp();
    row_to_tile<T>(p1 + n*(T*32), tile, lane);   __syncwarp();
    gemm_acc<T>(tile, Ws + 1024, lane, a);       __syncwarp();
    row_to_tile<T>(in + n*(T*32), tile, lane);   __syncwarp();
    gemm_acc<T>(tile, Ws + 2048, lane, a);       __syncwarp();
    acc_to_tile<T>(acc, tile, lane);             __syncwarp();
    gemm_acc<T>(tile, Ws + 3072, lane, a);

    float scl = g_affine[lane], bia = g_affine[32+lane];
    float gb  = gcb[lane];
    const float* xo = xold + (n*TIN + (TIN-T))*32 + lane;
    float* xn = xnew + n*(T*32) + lane;
    float sum = 0.f, sq = 0.f;
#pragma unroll
    for(int t = 0; t < T; t++){
        float v = a[t] + gb + xo[t*32]*scl + bia;
        xn[t*32] = v;
        sum += v; sq += v*v;
    }
    rs[tid] = sum; rq[tid] = sq;
    __syncthreads();
    if(tid < 32){
        float ts = 0.f, tq = 0.f;
#pragma unroll
        for(int w = 0; w < PW; w++){ ts += rs[w*32+tid]; tq += rq[w*32+tid]; }
        int sh = (blockIdx.x & 31)*64;
        atomicAdd(&g_statsS[sh+tid],    (double)ts);
        atomicAdd(&g_statsS[sh+32+tid], (double)tq);
    }
    if(tid == 0){
        __threadfence();
        int d = atomicAdd(&g_done, 1);
        isLast = (d == (int)gridDim.x - 1) ? 1 : 0;
    }
    __syncthreads();
    if(isLast){
        __threadfence();
        if(tid < 32){
            double S = 0.0, Q = 0.0;
            for(int k = 0; k < 32; k++){ S += g_statsS[k*64+tid]; Q += g_statsS[k*64+32+tid]; }
            double mu  = S*(double)invCnt;
            double var = Q*(double)invCnt - mu*mu;
            if(var < 0.0) var = 0.0;
            float scale = bng[tid] * rsqrtf((float)var + 1e-5f);
            g_affine[tid]    = scale;
            g_affine[32+tid] = bnb[tid] - (float)mu*scale;
        }
        __syncthreads();
        for(int j = tid; j < 2048; j += 128) g_statsS[j] = 0.0;
        if(tid == 0) g_done = 0;
    }
}

// ---------------- head ----------------
__global__ void __launch_bounds__(256) k_head(
    const float* __restrict__ sw_g, const float* __restrict__ sb_g,
    const float* __restrict__ w1, const float* __restrict__ b1,
    const float* __restrict__ w2, const float* __restrict__ b2,
    float* __restrict__ out)
{
    extern __shared__ float sm[];
    float* hlsT    = sm;            // 5120
    float* skipacc = sm + 5120;     // 4096
    float* wbuf    = sm + 9216;     // 8224
    float* y1s     = sm + 17440;    // 8192
    int tid = threadIdx.x;
    int n0 = blockIdx.x*16;

    for(int j = tid; j < 8*16*32; j += 256){
        int c = j & 31, m = (j>>5) & 15, l = j>>9;
        hlsT[(l*32+c)*20 + m] = g_hl[l*(N_NODES*32) + (n0+m)*32 + c];
    }
    float a[16];
    {
        float bs = 0.f;
        for(int l = 0; l < 8; l++) bs += sb_g[l*256+tid];
#pragma unroll
        for(int m = 0; m < 16; m++) a[m] = bs;
    }
    for(int l = 0; l < 8; l++){
        __syncthreads();
        for(int j = tid; j < 8192; j += 256){
            int c = j & 31, O = j >> 5;
            wbuf[c*257+O] = sw_g[l*8192 + O*32 + c];
        }
        __syncthreads();
#pragma unroll 4
        for(int c = 0; c < 32; c++){
            float w = wbuf[c*257+tid];
            const float4* hp = (const float4*)(hlsT + (l*32+c)*20);
#pragma unroll
            for(int m4 = 0; m4 < 4; m4++){
                float4 h4 = hp[m4];
                a[m4*4+0] += h4.x*w; a[m4*4+1] += h4.y*w;
                a[m4*4+2] += h4.z*w; a[m4*4+3] += h4.w*w;
            }
        }
    }
    __syncthreads();
#pragma unroll
    for(int m = 0; m < 16; m++) skipacc[m*256+tid] = fmaxf(a[m], 0.f);
    __syncthreads();

    const float4* sa = (const float4*)skipacc;
    for(int oo = 0; oo < 2; oo++){
        int o = oo*256 + tid;
        float acc[16];
#pragma unroll
        for(int m = 0; m < 16; m++) acc[m] = 0.f;
        const float4* wr = (const float4*)(w1 + o*256);
        for(int c4 = 0; c4 < 64; c4++){
            float4 w = wr[c4];
#pragma unroll
            for(int m = 0; m < 16; m++){
                float4 s = sa[m*64 + c4];
                acc[m] += w.x*s.x + w.y*s.y + w.z*s.z + w.w*s.w;
            }
        }
        float bb = b1[o];
#pragma unroll
        for(int m = 0; m < 16; m++) y1s[m*512+o] = fmaxf(acc[m] + bb, 0.f);
    }
    __syncthreads();

    for(int idx = tid; idx < 16*24; idx += 256){
        int m = idx/24, o = idx - 24*m;
        float acc = b2[o];
        const float4* wp = (const float4*)(w2 + o*512);
        const float4* yp = (const float4*)(y1s + m*512);
        for(int c4 = 0; c4 < 128; c4++){
            float4 ww = wp[c4], yy = yp[c4];
            acc += ww.x*yy.x + ww.y*yy.y + ww.z*yy.z + ww.w*yy.w;
        }
        out[(n0+m)*24 + o] = acc;
    }
}

// ---------------- host ----------------
static inline size_t conv_smem(bool enter){
    return (size_t)(4096 + (enter ? 128 : 0) + NPB*32*20) * 4;
}

extern "C" void kernel_launch(void* const* d_in, const int* in_sizes, int n_in,
                              void* d_out, int out_size)
{
    const float* inputs  = (const float*)d_in[0];
    const int*   esrc    = (const int*)  d_in[1];
    const int*   edst    = (const int*)  d_in[2];
    const float* enter_w = (const float*)d_in[3];
    const float* enter_b = (const float*)d_in[4];
    const float* filt_w  = (const float*)d_in[5];
    const float* filt_b  = (const float*)d_in[6];
    const float* gate_w  = (const float*)d_in[7];
    const float* gate_b  = (const float*)d_in[8];
    const float* gc_w    = (const float*)d_in[9];
    const float* gc_b    = (const float*)d_in[10];
    const float* skip_w  = (const float*)d_in[11];
    const float* skip_b  = (const float*)d_in[12];
    const float* bn_g    = (const float*)d_in[13];
    const float* bn_b    = (const float*)d_in[14];
    const float* out1_w  = (const float*)d_in[15];
    const float* out1_b  = (const float*)d_in[16];
    const float* out2_w  = (const float*)d_in[17];
    const float* out2_b  = (const float*)d_in[18];
    float* out = (float*)d_out;

    static int attr_set = 0;
    if(!attr_set){
        cudaFuncSetAttribute(k_head, cudaFuncAttributeMaxDynamicSharedMemorySize, 25632*4);
        attr_set = 1;
    }

    float *xA, *xB, *hl;
    __half *pA, *pB, *hh;
    cudaGetSymbolAddress((void**)&xA, g_xA);
    cudaGetSymbolAddress((void**)&xB, g_xB);
    cudaGetSymbolAddress((void**)&pA, g_pA);
    cudaGetSymbolAddress((void**)&pB, g_pB);
    cudaGetSymbolAddress((void**)&hh, g_h);
    cudaGetSymbolAddress((void**)&hl, g_hl);

    k_hist<<<(N_EDGES+255)/256, 256>>>(edst);
    k_scan<<<1, 1024>>>();

    const int GC = N_NODES/NPB;      // 2500
    const int GP = N_NODES/PW;       // 5000

    // fused: edge fill + conv layer 0 (enter fused)
    k_fillconv<<<1250 + GC, 256, conv_smem(true)>>>(
        esrc, edst,
        inputs, enter_w, enter_b,
        filt_w + 0*2048, filt_b + 0*32, gate_w + 0*2048, gate_b + 0*32,
        hl + 0*N_NODES*32, xA);
    k_hop<12><<<GP, 128>>>(hh, pA);
    k_hop<12><<<GP, 128>>>(pA, pB);
    k_propfin<12,13><<<GP, 128>>>(pB, pA, gc_w + 0*4096, xA, xB,
        gc_b + 0*32, bn_g + 0*32, bn_b + 0*32, 1.f/((float)N_NODES*12.f));

#define LAYER(l, TIN, DD, XIN, XNEW)                                                        \
    {                                                                                       \
        const int t = (TIN) - (DD);                                                         \
        k_conv<TIN, DD, false, false><<<GC, 256, conv_smem(false)>>>(                       \
            XIN, 0, 0,                                                                      \
            filt_w + (l)*2048, filt_b + (l)*32, gate_w + (l)*2048, gate_b + (l)*32,         \
            hl + (l)*N_NODES*32, 0);                                                        \
        k_hop<(TIN)-(DD)><<<GP, 128>>>(hh, pA);                                             \
        k_hop<(TIN)-(DD)><<<GP, 128>>>(pA, pB);                                             \
        k_propfin<(TIN)-(DD), TIN><<<GP, 128>>>(pB, pA, gc_w + (l)*4096, XIN, XNEW,         \
            gc_b + (l)*32, bn_g + (l)*32, bn_b + (l)*32, 1.f/((float)N_NODES*(float)t));    \
    }

    LAYER(1, 12, 2, xB, xA)
    LAYER(2, 10, 1, xA, xB)
    LAYER(3,  9, 2, xB, xA)
    LAYER(4,  7, 1, xA, xB)
    LAYER(5,  6, 2, xB, xA)
    LAYER(6,  4, 1, xA, xB)
#undef LAYER

    // layer 7: conv + hl only
    k_conv<3,2,false,true><<<GC, 256, conv_smem(false)>>>(
        xB, 0, 0,
        filt_w + 7*2048, filt_b + 7*32, gate_w + 7*2048, gate_b + 7*32,
        hl + 7*N_NODES*32, 0);

    k_head<<<N_NODES/16, 256, 25632*4>>>(skip_w, skip_b, out1_w, out1_b, out2_w, out2_b, out);
}

// round 10
// speedup vs baseline: 1.2408x; 1.0306x over previous
#include <cuda_runtime.h>
#include <cuda_fp16.h>
#include <math.h>

#define N_NODES 20000
#define N_EDGES 320000
#define NPB 8
#define PW 4      // warps (nodes) per prop block

// ---------------- device scratch ----------------
__device__ float  g_xA[N_NODES*13*32];
__device__ float  g_xB[N_NODES*13*32];
__device__ __half g_h [N_NODES*12*32];
__device__ __half g_pA[N_NODES*12*32];
__device__ __half g_pB[N_NODES*12*32];
__device__ float  g_hl[8*N_NODES*32];
__device__ int    g_rowptr[N_NODES+1];
__device__ int    g_curs[N_NODES];
__device__ int    g_cnt[N_NODES];
__device__ float  g_invdeg[N_NODES];
__device__ int    g_col[N_EDGES];
__device__ double g_statsS[32*64];
__device__ float  g_affine[64];
__device__ int    g_done;

__device__ __forceinline__ __half2 H2(unsigned int u){ return *reinterpret_cast<__half2*>(&u); }
__device__ __forceinline__ unsigned int U2(__half2 h){ return *reinterpret_cast<unsigned int*>(&h); }

// ---------------- packed f32x2 helpers ----------------
union Pun4 { float4 f; ulonglong2 u; };

__device__ __forceinline__ unsigned long long ffma2(unsigned long long a, unsigned long long b, unsigned long long c){
    unsigned long long d;
    asm("fma.rn.f32x2 %0, %1, %2, %3;" : "=l"(d) : "l"(a), "l"(b), "l"(c));
    return d;
}
__device__ __forceinline__ unsigned long long packf2(float lo, float hi){
    unsigned long long d;
    asm("mov.b64 %0, {%1, %2};" : "=l"(d) : "f"(lo), "f"(hi));
    return d;
}
__device__ __forceinline__ float2 unpackf2(unsigned long long v){
    float2 r;
    asm("mov.b64 {%0, %1}, %2;" : "=f"(r.x), "=f"(r.y) : "l"(v));
    return r;
}

// ---------------- setup ----------------
__global__ void k_hist(const int* __restrict__ dst){
    int i = blockIdx.x*256 + threadIdx.x;
    if(i < 64) g_affine[i] = (i < 32) ? 1.f : 0.f;
    if(i < N_EDGES) atomicAdd(&g_cnt[dst[i]], 1);
}

__global__ void k_scan(){
    const int CH = 20;
    int tid = threadIdx.x;
    int b0 = tid*CH; if(b0 > N_NODES) b0 = N_NODES;
    int b1 = b0 + CH; if(b1 > N_NODES) b1 = N_NODES;
    int sum = 0;
    for(int i = b0; i < b1; i++) sum += g_cnt[i];
    int lane = tid & 31, w = tid >> 5;
    int v = sum;
#pragma unroll
    for(int o = 1; o < 32; o <<= 1){
        int t = __shfl_up_sync(0xffffffffu, v, o);
        if(lane >= o) v += t;
    }
    __shared__ int wsum[32];
    if(lane == 31) wsum[w] = v;
    __syncthreads();
    if(w == 0){
        int x = wsum[lane];
#pragma unroll
        for(int o = 1; o < 32; o <<= 1){
            int t = __shfl_up_sync(0xffffffffu, x, o);
            if(lane >= o) x += t;
        }
        wsum[lane] = x;
    }
    __syncthreads();
    int pre = v - sum + ((w > 0) ? wsum[w-1] : 0);
    int run = pre;
    for(int i = b0; i < b1; i++){
        int c = g_cnt[i];
        g_curs[i] = run;
        run += c;
        g_rowptr[i+1] = run;
        g_invdeg[i] = 1.f/(float)(c > 0 ? c : 1);
        g_cnt[i] = 0;
    }
    if(tid == 0) g_rowptr[0] = 0;
}

// ---------------- conv body (flat 256 threads; 8 nodes): gated conv -> h(fp16), hl ----------------
template<int TIN, int D, bool ENTER, bool LAST>
__device__ __forceinline__ void conv_body(
    int n0, float* sm,
    const float* __restrict__ xin,
    const float* __restrict__ ew, const float* __restrict__ eb,
    const float* __restrict__ fw_g, const float* __restrict__ fb_g,
    const float* __restrict__ gw_g, const float* __restrict__ gb_g,
    float* __restrict__ hl_out, float* __restrict__ xsave)
{
    constexpr int TOUT = TIN - D;
    constexpr int NP2  = TOUT/2;
    constexpr int ODD  = TOUT & 1;
    constexpr int NQ   = (TIN + 3)/4;
    constexpr int TP   = 20;
    float* wq  = sm;
    float* ews = sm + 4096;
    float* xs  = ews + (ENTER ? 128 : 0);

    int tid = threadIdx.x;
    int tx = tid & 31, ty = tid >> 5;
    for(int j = tid; j < 1024; j += 256){
        int o = j & 31, i = j >> 5;
        float4 v;
        v.x = fw_g[(o*32+i)*2+0];
        v.y = fw_g[(o*32+i)*2+1];
        v.z = gw_g[(o*32+i)*2+0];
        v.w = gw_g[(o*32+i)*2+1];
        ((float4*)wq)[j] = v;
    }
    if(ENTER){
        if(tid < 96) ews[tid] = ew[tid];
        if(tid < 32) ews[96+tid] = eb[tid];
    }
    __syncthreads();

    int n = n0 + ty;
    float* xrow = xs + ty*(32*TP);
    if(ENTER){
        const float* ip = xin + n*(TIN*3);
        float we0 = ews[tx*3+0], we1 = ews[tx*3+1], we2 = ews[tx*3+2], be = ews[96+tx];
#pragma unroll
        for(int tt = 0; tt < TIN; tt++){
            float v = be + we0*ip[tt*3+0] + we1*ip[tt*3+1] + we2*ip[tt*3+2];
            xrow[tx*TP+tt] = v;
            xsave[(n*TIN+tt)*32+tx] = v;
        }
    } else {
        float scl = g_affine[tx], bia = g_affine[32+tx];
        const float* xp = xin + n*(TIN*32);
#pragma unroll
        for(int tt = 0; tt < TIN; tt++)
            xrow[tx*TP+tt] = xp[tt*32+tx]*scl + bia;
    }
    __syncwarp();

    float fb = fb_g[tx], gb = gb_g[tx];
    unsigned long long f2[NP2 ? NP2 : 1], g2[NP2 ? NP2 : 1];
    {
        unsigned long long fbp = packf2(fb, fb), gbp = packf2(gb, gb);
#pragma unroll
        for(int j = 0; j < NP2; j++){ f2[j] = fbp; g2[j] = gbp; }
    }
    float fod = fb, god = gb;

#pragma unroll
    for(int i = 0; i < 32; i++){
        float4 w4 = ((const float4*)wq)[i*32+tx];
        unsigned long long W0f = packf2(w4.x, w4.x), W1f = packf2(w4.y, w4.y);
        unsigned long long W0g = packf2(w4.z, w4.z), W1g = packf2(w4.w, w4.w);
        Pun4 t4[NQ];
        const float4* xq = (const float4*)(xrow + i*TP);
#pragma unroll
        for(int q = 0; q < NQ; q++) t4[q].f = xq[q];
        float xv[NQ*4];
#pragma unroll
        for(int q = 0; q < NQ; q++){
            xv[q*4+0] = t4[q].f.x; xv[q*4+1] = t4[q].f.y;
            xv[q*4+2] = t4[q].f.z; xv[q*4+3] = t4[q].f.w;
        }
#pragma unroll
        for(int j = 0; j < NP2; j++){
            unsigned long long Aj = (j & 1) ? t4[j>>1].u.y : t4[j>>1].u.x;
            f2[j] = ffma2(Aj, W0f, f2[j]);
            g2[j] = ffma2(Aj, W0g, g2[j]);
            if(D & 1){
                unsigned long long Sj = packf2(xv[2*j+1], xv[2*j+2]);
                f2[j] = ffma2(Sj, W1f, f2[j]);
                g2[j] = ffma2(Sj, W1g, g2[j]);
            } else {
                int j1 = j + D/2;
                unsigned long long Aj1 = (j1 & 1) ? t4[j1>>1].u.y : t4[j1>>1].u.x;
                f2[j] = ffma2(Aj1, W1f, f2[j]);
                g2[j] = ffma2(Aj1, W1g, g2[j]);
            }
        }
        if(ODD){
            float x0 = xv[TOUT-1], x1 = xv[TOUT-1+D];
            fod += w4.x*x0 + w4.y*x1;
            god += w4.z*x0 + w4.w*x1;
        }
    }

    if(!LAST){
        float hlast = 0.f;
#pragma unroll
        for(int j = 0; j < NP2; j++){
            float2 ff = unpackf2(f2[j]);
            float2 gg = unpackf2(g2[j]);
            float h0 = tanhf(ff.x) * (1.f/(1.f + expf(-gg.x)));
            float h1 = tanhf(ff.y) * (1.f/(1.f + expf(-gg.y)));
            g_h[(n*TOUT + 2*j)*32+tx]   = __float2half_rn(h0);
            g_h[(n*TOUT + 2*j+1)*32+tx] = __float2half_rn(h1);
            if(2*j+1 == TOUT-1) hlast = h1;
        }
        if(ODD){
            float h = tanhf(fod) * (1.f/(1.f + expf(-god)));
            g_h[(n*TOUT + TOUT-1)*32+tx] = __float2half_rn(h);
            hlast = h;
        }
        hl_out[n*32+tx] = hlast;
    } else {
        float h = tanhf(fod) * (1.f/(1.f + expf(-god)));
        hl_out[n*32+tx] = h;
    }
}

template<int TIN, int D, bool ENTER, bool LAST>
__global__ void __launch_bounds__(256) k_conv(
    const float* __restrict__ xin,
    const float* __restrict__ ew, const float* __restrict__ eb,
    const float* __restrict__ fw_g, const float* __restrict__ fb_g,
    const float* __restrict__ gw_g, const float* __restrict__ gb_g,
    float* __restrict__ hl_out, float* __restrict__ xsave)
{
    extern __shared__ float sm[];
    conv_body<TIN,D,ENTER,LAST>(blockIdx.x*NPB, sm, xin, ew, eb,
        fw_g, fb_g, gw_g, gb_g, hl_out, xsave);
}

// fused: blocks [0,1250) do edge fill; rest do conv layer 0
__global__ void __launch_bounds__(256) k_fillconv(
    const int* __restrict__ src, const int* __restrict__ dst,
    const float* __restrict__ xin,
    const float* __restrict__ ew, const float* __restrict__ eb,
    const float* __restrict__ fw_g, const float* __restrict__ fb_g,
    const float* __restrict__ gw_g, const float* __restrict__ gb_g,
    float* __restrict__ hl_out, float* __restrict__ xsave)
{
    extern __shared__ float sm[];
    if(blockIdx.x < 1250){
        int e = blockIdx.x*256 + threadIdx.x;
        if(e < N_EDGES){
            int pos = atomicAdd(&g_curs[dst[e]], 1);
            g_col[pos] = src[e];
        }
    } else {
        conv_body<13,1,true,false>((blockIdx.x-1250)*NPB, sm, xin, ew, eb,
            fw_g, fb_g, gw_g, gb_g, hl_out, xsave);
    }
}

// ---------------- fp16 gather core: one warp per node, contiguous edges ----------------
template<int T>
__device__ __forceinline__ void gather_row_h(const uint4* __restrict__ in,
                                             int n, int lane, float* acc)
{
    constexpr int R  = T*4;
    constexpr int NV = (R + 31)/32;
    constexpr int EG = (NV == 1) ? 8 : 4;
#pragma unroll
    for(int k = 0; k < NV*8; k++) acc[k] = 0.f;
    int beg = g_rowptr[n], end = g_rowptr[n+1];
    int e = beg;
    for(; e + EG <= end; e += EG){
        int s[EG];
#pragma unroll
        for(int j = 0; j < EG; j++) s[j] = g_col[e+j];
        uint4 q[EG*NV];
#pragma unroll
        for(int j = 0; j < EG; j++){
#pragma unroll
            for(int v = 0; v < NV; v++){
                int idx = v*32 + lane;
                if(idx < R) q[j*NV+v] = in[s[j]*R + idx];
            }
        }
#pragma unroll
        for(int v = 0; v < NV; v++){
            int idx = v*32 + lane;
            if(idx < R){
                __half2 tx_[EG], ty_[EG], tz_[EG], tw_[EG];
#pragma unroll
                for(int j = 0; j < EG; j++){
                    tx_[j] = H2(q[j*NV+v].x); ty_[j] = H2(q[j*NV+v].y);
                    tz_[j] = H2(q[j*NV+v].z); tw_[j] = H2(q[j*NV+v].w);
                }
#pragma unroll
                for(int st = 1; st < EG; st <<= 1){
#pragma unroll
                    for(int j = 0; j < EG; j += 2*st){
                        tx_[j] = __hadd2(tx_[j], tx_[j+st]);
                        ty_[j] = __hadd2(ty_[j], ty_[j+st]);
                        tz_[j] = __hadd2(tz_[j], tz_[j+st]);
                        tw_[j] = __hadd2(tw_[j], tw_[j+st]);
                    }
                }
                float2 f;
                f = __half22float2(tx_[0]); acc[v*8+0] += f.x; acc[v*8+1] += f.y;
                f = __half22float2(ty_[0]); acc[v*8+2] += f.x; acc[v*8+3] += f.y;
                f = __half22float2(tz_[0]); acc[v*8+4] += f.x; acc[v*8+5] += f.y;
                f = __half22float2(tw_[0]); acc[v*8+6] += f.x; acc[v*8+7] += f.y;
            }
        }
    }
    for(; e < end; e++){
        int s0 = g_col[e];
        const uint4* r0 = in + s0*R;
#pragma unroll
        for(int v = 0; v < NV; v++){
            int idx = v*32 + lane;
            if(idx < R){
                uint4 q = r0[idx];
                float2 f;
                f = __half22float2(H2(q.x)); acc[v*8+0] += f.x; acc[v*8+1] += f.y;
                f = __half22float2(H2(q.y)); acc[v*8+2] += f.x; acc[v*8+3] += f.y;
                f = __half22float2(H2(q.z)); acc[v*8+4] += f.x; acc[v*8+5] += f.y;
                f = __half22float2(H2(q.w)); acc[v*8+6] += f.x; acc[v*8+7] += f.y;
            }
        }
    }
    float iv = g_invdeg[n];
#pragma unroll
    for(int k = 0; k < NV*8; k++) acc[k] *= iv;
}

// scatter gathered fp32 values into smem tile (t-major, 32 ch)
template<int T>
__device__ __forceinline__ void acc_to_tile(const float* acc, float* tile, int lane){
    constexpr int R  = T*4;
    constexpr int NV = (R + 31)/32;
#pragma unroll
    for(int v = 0; v < NV; v++){
        int idx = v*32 + lane;
        if(idx < R){
            int t = idx >> 2, c0 = (idx & 3) << 3;
            float4* tp = (float4*)(tile + t*32 + c0);
            tp[0] = make_float4(acc[v*8+0], acc[v*8+1], acc[v*8+2], acc[v*8+3]);
            tp[1] = make_float4(acc[v*8+4], acc[v*8+5], acc[v*8+6], acc[v*8+7]);
        }
    }
}

// load an fp16 row (own node, coalesced) into the fp32 smem tile
template<int T>
__device__ __forceinline__ void row_to_tile(const __half* __restrict__ row,
                                            float* tile, int lane){
    constexpr int R  = T*4;
    constexpr int NV = (R + 31)/32;
    const uint4* r4 = (const uint4*)row;
#pragma unroll
    for(int v = 0; v < NV; v++){
        int idx = v*32 + lane;
        if(idx < R){
            uint4 q = r4[idx];
            int t = idx >> 2, c0 = (idx & 3) << 3;
            float4* tp = (float4*)(tile + t*32 + c0);
            float2 fx = __half22float2(H2(q.x));
            float2 fy = __half22float2(H2(q.y));
            float2 fz = __half22float2(H2(q.z));
            float2 fw = __half22float2(H2(q.w));
            tp[0] = make_float4(fx.x, fx.y, fy.x, fy.y);
            tp[1] = make_float4(fz.x, fz.y, fw.x, fw.y);
        }
    }
}

// packed GEMM: a2[t] += pairs over K of tile[t][c] * W[c][lane]
template<int T>
__device__ __forceinline__ void gemm_acc2(const float* tile, const float* Ws,
                                          int lane, unsigned long long* a2){
    const ulonglong2* tp = (const ulonglong2*)tile;
#pragma unroll
    for(int c4 = 0; c4 < 8; c4++){
        float w0 = Ws[(c4*4+0)*32+lane];
        float w1 = Ws[(c4*4+1)*32+lane];
        float w2 = Ws[(c4*4+2)*32+lane];
        float w3 = Ws[(c4*4+3)*32+lane];
        unsigned long long W01 = packf2(w0, w1);
        unsigned long long W23 = packf2(w2, w3);
#pragma unroll
        for(int t = 0; t < T; t++){
            ulonglong2 sv = tp[t*4+c4/2*1];   // placeholder, fixed below
        }
        // NOTE: proper indexing below
#pragma unroll
        for(int t = 0; t < T; t++){
            const ulonglong2* rp = (const ulonglong2*)(tile + t*32 + c4*4);
            ulonglong2 sv = rp[0];
            a2[t] = ffma2(sv.x, W01, a2[t]);
            a2[t] = ffma2(sv.y, W23, a2[t]);
        }
        break;
    }
    // full loop (the above first-iteration pattern expanded cleanly)
#pragma unroll
    for(int c4 = 1; c4 < 8; c4++){
        float w0 = Ws[(c4*4+0)*32+lane];
        float w1 = Ws[(c4*4+1)*32+lane];
        float w2 = Ws[(c4*4+2)*32+lane];
        float w3 = Ws[(c4*4+3)*32+lane];
        unsigned long long W01 = packf2(w0, w1);
        unsigned long long W23 = packf2(w2, w3);
#pragma unroll
        for(int t = 0; t < T; t++){
            const ulonglong2* rp = (const ulonglong2*)(tile + t*32 + c4*4);
            ulonglong2 sv = rp[0];
            a2[t] = ffma2(sv.x, W01, a2[t]);
            a2[t] = ffma2(sv.y, W23, a2[t]);
        }
    }
}

// ---------------- pure diffusion hop: out = A*in (fp16 -> fp16) ----------------
template<int T>
__global__ void __launch_bounds__(128) k_hop(
    const __half* __restrict__ in, __half* __restrict__ out)
{
    constexpr int R  = T*4;
    constexpr int NV = (R + 31)/32;
    int tid = threadIdx.x, lane = tid & 31, wid = tid >> 5;
    int n = blockIdx.x*PW + wid;
    float acc[NV*8];
    gather_row_h<T>((const uint4*)in, n, lane, acc);
    uint4* cp = (uint4*)out + n*R;
#pragma unroll
    for(int v = 0; v < NV; v++){
        int idx = v*32 + lane;
        if(idx < R){
            uint4 q;
            q.x = U2(__floats2half2_rn(acc[v*8+0], acc[v*8+1]));
            q.y = U2(__floats2half2_rn(acc[v*8+2], acc[v*8+3]));
            q.z = U2(__floats2half2_rn(acc[v*8+4], acc[v*8+5]));
            q.w = U2(__floats2half2_rn(acc[v*8+6], acc[v*8+7]));
            cp[idx] = q;
        }
    }
}

// ---------------- propfin: p3 = A*p2 ; x = h@W0+p1@W1+p2@W2+p3@W3 + gcb + affine(xold); BN ----------------
template<int T, int TIN>
__global__ void __launch_bounds__(128) k_propfin(
    const __half* __restrict__ in,        // p2
    const __half* __restrict__ p1,
    const float* __restrict__ Wk4,        // 4x 32x32
    const float* __restrict__ xold, float* __restrict__ xnew,
    const float* __restrict__ gcb,
    const float* __restrict__ bng, const float* __restrict__ bnb, float invCnt)
{
    constexpr int R  = T*4;
    constexpr int NV = (R + 31)/32;
    __shared__ float Ws[4096];
    __shared__ __align__(16) float smS[PW*12*32];
    __shared__ float rs[32*PW], rq[32*PW];
    __shared__ int isLast;
    int tid = threadIdx.x, lane = tid & 31, wid = tid >> 5;
    for(int j = tid; j < 4096; j += 128) Ws[j] = Wk4[j];
    __syncthreads();

    int n = blockIdx.x*PW + wid;
    float acc[NV*8];
    gather_row_h<T>((const uint4*)in, n, lane, acc);   // p3

    unsigned long long a2[T];
#pragma unroll
    for(int t = 0; t < T; t++) a2[t] = 0ull;
    float* tile = smS + wid*(T*32);

    row_to_tile<T>(g_h + n*(T*32), tile, lane);  __syncwarp();
    gemm_acc2<T>(tile, Ws,        lane, a2);     __syncwarp();
    row_to_tile<T>(p1 + n*(T*32), tile, lane);   __syncwarp();
    gemm_acc2<T>(tile, Ws + 1024, lane, a2);     __syncwarp();
    row_to_tile<T>(in + n*(T*32), tile, lane);   __syncwarp();
    gemm_acc2<T>(tile, Ws + 2048, lane, a2);     __syncwarp();
    acc_to_tile<T>(acc, tile, lane);             __syncwarp();
    gemm_acc2<T>(tile, Ws + 3072, lane, a2);

    float scl = g_affine[lane], bia = g_affine[32+lane];
    float gb  = gcb[lane];
    const float* xo = xold + (n*TIN + (TIN-T))*32 + lane;
    float* xn = xnew + n*(T*32) + lane;
    float sum = 0.f, sq = 0.f;
#pragma unroll
    for(int t = 0; t < T; t++){
        float2 av = unpackf2(a2[t]);
        float v = (av.x + av.y) + gb + xo[t*32]*scl + bia;
        xn[t*32] = v;
        sum += v; sq += v*v;
    }
    rs[tid] = sum; rq[tid] = sq;
    __syncthreads();
    if(tid < 32){
        float ts = 0.f, tq = 0.f;
#pragma unroll
        for(int w = 0; w < PW; w++){ ts += rs[w*32+tid]; tq += rq[w*32+tid]; }
        int sh = (blockIdx.x & 31)*64;
        atomicAdd(&g_statsS[sh+tid],    (double)ts);
        atomicAdd(&g_statsS[sh+32+tid], (double)tq);
    }
    if(tid == 0){
        __threadfence();
        int d = atomicAdd(&g_done, 1);
        isLast = (d == (int)gridDim.x - 1) ? 1 : 0;
    }
    __syncthreads();
    if(isLast){
        __threadfence();
        if(tid < 32){
            double S = 0.0, Q = 0.0;
            for(int k = 0; k < 32; k++){ S += g_statsS[k*64+tid]; Q += g_statsS[k*64+32+tid]; }
            double mu  = S*(double)invCnt;
            double var = Q*(double)invCnt - mu*mu;
            if(var < 0.0) var = 0.0;
            float scale = bng[tid] * rsqrtf((float)var + 1e-5f);
            g_affine[tid]    = scale;
            g_affine[32+tid] = bnb[tid] - (float)mu*scale;
        }
        __syncthreads();
        for(int j = tid; j < 2048; j += 128) g_statsS[j] = 0.0;
        if(tid == 0) g_done = 0;
    }
}

// ---------------- head (f32x2 packed) ----------------
__global__ void __launch_bounds__(256) k_head(
    const float* __restrict__ sw_g, const float* __restrict__ sb_g,
    const float* __restrict__ w1, const float* __restrict__ b1,
    const float* __restrict__ w2, const float* __restrict__ b2,
    float* __restrict__ out)
{
    extern __shared__ float sm[];
    float* hlsT    = sm;            // 5120
    float* skipacc = sm + 5120;     // 4096
    float* wbuf    = sm + 9216;     // 8224
    float* y1s     = sm + 17440;    // 8192
    int tid = threadIdx.x;
    int n0 = blockIdx.x*16;

    for(int j = tid; j < 8*16*32; j += 256){
        int c = j & 31, m = (j>>5) & 15, l = j>>9;
        hlsT[(l*32+c)*20 + m] = g_hl[l*(N_NODES*32) + (n0+m)*32 + c];
    }
    unsigned long long a2m[8];
    {
        float bs = 0.f;
        for(int l = 0; l < 8; l++) bs += sb_g[l*256+tid];
        unsigned long long bsp = packf2(bs, bs);
#pragma unroll
        for(int j = 0; j < 8; j++) a2m[j] = bsp;
    }
    for(int l = 0; l < 8; l++){
        __syncthreads();
        for(int j = tid; j < 8192; j += 256){
            int c = j & 31, O = j >> 5;
            wbuf[c*257+O] = sw_g[l*8192 + O*32 + c];
        }
        __syncthreads();
#pragma unroll 4
        for(int c = 0; c < 32; c++){
            float w = wbuf[c*257+tid];
            unsigned long long W = packf2(w, w);
            const ulonglong2* hp = (const ulonglong2*)(hlsT + (l*32+c)*20);
#pragma unroll
            for(int m4 = 0; m4 < 4; m4++){
                ulonglong2 h2 = hp[m4];
                a2m[m4*2+0] = ffma2(h2.x, W, a2m[m4*2+0]);
                a2m[m4*2+1] = ffma2(h2.y, W, a2m[m4*2+1]);
            }
        }
    }
    __syncthreads();
#pragma unroll
    for(int j = 0; j < 8; j++){
        float2 v = unpackf2(a2m[j]);
        skipacc[(2*j)*256+tid]   = fmaxf(v.x, 0.f);
        skipacc[(2*j+1)*256+tid] = fmaxf(v.y, 0.f);
    }
    __syncthreads();

    for(int oo = 0; oo < 2; oo++){
        int o = oo*256 + tid;
        unsigned long long acc2[16];
#pragma unroll
        for(int m = 0; m < 16; m++) acc2[m] = 0ull;
        const ulonglong2* wr = (const ulonglong2*)(w1 + o*256);
        const ulonglong2* sa = (const ulonglong2*)skipacc;
        for(int c4 = 0; c4 < 64; c4++){
            ulonglong2 w = wr[c4];
#pragma unroll
            for(int m = 0; m < 16; m++){
                ulonglong2 s = sa[m*64 + c4];
                acc2[m] = ffma2(s.x, w.x, acc2[m]);
                acc2[m] = ffma2(s.y, w.y, acc2[m]);
            }
        }
        float bb = b1[o];
#pragma unroll
        for(int m = 0; m < 16; m++){
            float2 v = unpackf2(acc2[m]);
            y1s[m*512+o] = fmaxf(v.x + v.y + bb, 0.f);
        }
    }
    __syncthreads();

    for(int idx = tid; idx < 16*24; idx += 256){
        int m = idx/24, o = idx - 24*m;
        unsigned long long acc2 = 0ull;
        const ulonglong2* wp = (const ulonglong2*)(w2 + o*512);
        const ulonglong2* yp = (const ulonglong2*)(y1s + m*512);
        for(int c4 = 0; c4 < 128; c4++){
            ulonglong2 ww = wp[c4], yy = yp[c4];
            acc2 = ffma2(ww.x, yy.x, acc2);
            acc2 = ffma2(ww.y, yy.y, acc2);
        }
        float2 v = unpackf2(acc2);
        out[(n0+m)*24 + o] = b2[o] + v.x + v.y;
    }
}

// ---------------- host ----------------
static inline size_t conv_smem(bool enter){
    return (size_t)(4096 + (enter ? 128 : 0) + NPB*32*20) * 4;
}

extern "C" void kernel_launch(void* const* d_in, const int* in_sizes, int n_in,
                              void* d_out, int out_size)
{
    const float* inputs  = (const float*)d_in[0];
    const int*   esrc    = (const int*)  d_in[1];
    const int*   edst    = (const int*)  d_in[2];
    const float* enter_w = (const float*)d_in[3];
    const float* enter_b = (const float*)d_in[4];
    const float* filt_w  = (const float*)d_in[5];
    const float* filt_b  = (const float*)d_in[6];
    const float* gate_w  = (const float*)d_in[7];
    const float* gate_b  = (const float*)d_in[8];
    const float* gc_w    = (const float*)d_in[9];
    const float* gc_b    = (const float*)d_in[10];
    const float* skip_w  = (const float*)d_in[11];
    const float* skip_b  = (const float*)d_in[12];
    const float* bn_g    = (const float*)d_in[13];
    const float* bn_b    = (const float*)d_in[14];
    const float* out1_w  = (const float*)d_in[15];
    const float* out1_b  = (const float*)d_in[16];
    const float* out2_w  = (const float*)d_in[17];
    const float* out2_b  = (const float*)d_in[18];
    float* out = (float*)d_out;

    static int attr_set = 0;
    if(!attr_set){
        cudaFuncSetAttribute(k_head, cudaFuncAttributeMaxDynamicSharedMemorySize, 25632*4);
        attr_set = 1;
    }

    float *xA, *xB, *hl;
    __half *pA, *pB, *hh;
    cudaGetSymbolAddress((void**)&xA, g_xA);
    cudaGetSymbolAddress((void**)&xB, g_xB);
    cudaGetSymbolAddress((void**)&pA, g_pA);
    cudaGetSymbolAddress((void**)&pB, g_pB);
    cudaGetSymbolAddress((void**)&hh, g_h);
    cudaGetSymbolAddress((void**)&hl, g_hl);

    k_hist<<<(N_EDGES+255)/256, 256>>>(edst);
    k_scan<<<1, 1024>>>();

    const int GC = N_NODES/NPB;      // 2500
    const int GP = N_NODES/PW;       // 5000

    // fused: edge fill + conv layer 0 (enter fused)
    k_fillconv<<<1250 + GC, 256, conv_smem(true)>>>(
        esrc, edst,
        inputs, enter_w, enter_b,
        filt_w + 0*2048, filt_b + 0*32, gate_w + 0*2048, gate_b + 0*32,
        hl + 0*N_NODES*32, xA);
    k_hop<12><<<GP, 128>>>(hh, pA);
    k_hop<12><<<GP, 128>>>(pA, pB);
    k_propfin<12,13><<<GP, 128>>>(pB, pA, gc_w + 0*4096, xA, xB,
        gc_b + 0*32, bn_g + 0*32, bn_b + 0*32, 1.f/((float)N_NODES*12.f));

#define LAYER(l, TIN, DD, XIN, XNEW)                                                        \
    {                                                                                       \
        const int t = (TIN) - (DD);                                                         \
        k_conv<TIN, DD, false, false><<<GC, 256, conv_smem(false)>>>(                       \
            XIN, 0, 0,                                                                      \
            filt_w + (l)*2048, filt_b + (l)*32, gate_w + (l)*2048, gate_b + (l)*32,         \
            hl + (l)*N_NODES*32, 0);                                                        \
        k_hop<(TIN)-(DD)><<<GP, 128>>>(hh, pA);                                             \
        k_hop<(TIN)-(DD)><<<GP, 128>>>(pA, pB);                                             \
        k_propfin<(TIN)-(DD), TIN><<<GP, 128>>>(pB, pA, gc_w + (l)*4096, XIN, XNEW,         \
            gc_b + (l)*32, bn_g + (l)*32, bn_b + (l)*32, 1.f/((float)N_NODES*(float)t));    \
    }

    LAYER(1, 12, 2, xB, xA)
    LAYER(2, 10, 1, xA, xB)
    LAYER(3,  9, 2, xB, xA)
    LAYER(4,  7, 1, xA, xB)
    LAYER(5,  6, 2, xB, xA)
    LAYER(6,  4, 1, xA, xB)
#undef LAYER

    // layer 7: conv + hl only
    k_conv<3,2,false,true><<<GC, 256, conv_smem(false)>>>(
        xB, 0, 0,
        filt_w + 7*2048, filt_b + 7*32, gate_w + 7*2048, gate_b + 7*32,
        hl + 7*N_NODES*32, 0);

    k_head<<<N_NODES/16, 256, 25632*4>>>(skip_w, skip_b, out1_w, out1_b, out2_w, out2_b, out);
}